// round 3
// baseline (speedup 1.0000x reference)
#include <cuda_runtime.h>
#include <cuda_bf16.h>
#include <mma.h>
#include <math.h>

using namespace nvcuda;

#define BB 2
#define SS 2048
#define DD 1024
#define HH 16
#define DHH 64
#define MM (BB * SS)

// Scratch (allocation-free rule -> device globals)
__device__ float g_Q[(size_t)BB * SS * DD];
__device__ float g_K[(size_t)BB * SS * DD];
__device__ float g_V[(size_t)BB * SS * DD];
__device__ float g_AO[(size_t)BB * SS * DD];

// FFMA-only exp (scores bounded ~ +/-10, no overflow issues; err ~2e-6 rel)
__device__ __forceinline__ float fexp(float x) {
    float y = x * 1.4426950408889634f;      // x / ln2
    int   n = __float2int_rn(y);
    float f = y - (float)n;                 // [-0.5, 0.5]
    float z = f * 0.69314718055994531f;     // f * ln2
    float p = 8.3333333e-3f;
    p = fmaf(p, z, 4.1666667e-2f);
    p = fmaf(p, z, 1.6666667e-1f);
    p = fmaf(p, z, 5.0e-1f);
    p = fmaf(p, z, 1.0f);
    p = fmaf(p, z, 1.0f);
    return __int_as_float(__float_as_int(p) + (n << 23));
}

__device__ __forceinline__ void split_tf32(float x, float& hi, float& lo) {
    hi = wmma::__float_to_tf32(x);
    lo = wmma::__float_to_tf32(x - hi);
}

// ---------------------------------------------------------------------------
// 3xTF32 GEMM: C[M,1024] = A[M,1024] @ W + bias. Handles up to 3 weight
// matrices per launch (QKV fused): which = blockIdx.x / 8.
// Block tile 128x128, BK=16, 8 warps (warp tile 64x32), reg-prefetch pipeline.
// ---------------------------------------------------------------------------
__global__ __launch_bounds__(256) void gemm3_kernel(
    const float* __restrict__ A,
    const float* __restrict__ W0, const float* __restrict__ W1, const float* __restrict__ W2,
    const float* __restrict__ b0, const float* __restrict__ b1, const float* __restrict__ b2,
    float* __restrict__ C0, float* __restrict__ C1, float* __restrict__ C2)
{
    __shared__ float sm[8192];              // 32KB
    float* Ah = sm;                         // [16][128] (k-major, transposed)
    float* Al = sm + 2048;
    float* Bh = sm + 4096;                  // [16][128]
    float* Bl = sm + 6144;

    const int tid = threadIdx.x;
    const int wid = tid >> 5;
    const int which = blockIdx.x >> 3;
    const float* W    = (which == 0) ? W0 : (which == 1) ? W1 : W2;
    const float* bias = (which == 0) ? b0 : (which == 1) ? b1 : b2;
    float*       C    = (which == 0) ? C0 : (which == 1) ? C1 : C2;
    const int bCol = (blockIdx.x & 7) * 128;
    const int bRow = blockIdx.y * 128;
    const int warp_m = wid >> 2;            // 0..1 -> rows warp_m*64
    const int warp_n = wid & 3;             // 0..3 -> cols warp_n*32
    const int K = DD, N = DD;

    wmma::fragment<wmma::accumulator, 16, 16, 8, float> acc[4][2];
#pragma unroll
    for (int m = 0; m < 4; m++)
#pragma unroll
        for (int n = 0; n < 2; n++) wmma::fill_fragment(acc[m][n], 0.0f);

    // prefetch regs
    float4 aReg[2], bReg[2];
    // A mapping: id4 -> m_l = id4/4 (0..127), k_l = (id4%4)*4
    // B mapping: id4 -> r = id4/32 (0..15), c = (id4%32)*4
#pragma unroll
    for (int v = 0; v < 2; v++) {
        int id4 = tid + v * 256;
        int am = id4 >> 2, ak = (id4 & 3) * 4;
        aReg[v] = *reinterpret_cast<const float4*>(&A[(size_t)(bRow + am) * K + ak]);
        int br = id4 >> 5, bc = (id4 & 31) * 4;
        bReg[v] = *reinterpret_cast<const float4*>(&W[(size_t)br * N + bCol + bc]);
    }

    for (int k0 = 0; k0 < K; k0 += 16) {
        // store prefetched tile (with tf32 hi/lo split)
#pragma unroll
        for (int v = 0; v < 2; v++) {
            int id4 = tid + v * 256;
            int am = id4 >> 2, ak = (id4 & 3) * 4;
            float av[4] = {aReg[v].x, aReg[v].y, aReg[v].z, aReg[v].w};
#pragma unroll
            for (int j = 0; j < 4; j++) {
                float hi, lo; split_tf32(av[j], hi, lo);
                Ah[(ak + j) * 128 + am] = hi;
                Al[(ak + j) * 128 + am] = lo;
            }
            int br = id4 >> 5, bc = (id4 & 31) * 4;
            float bv[4] = {bReg[v].x, bReg[v].y, bReg[v].z, bReg[v].w};
#pragma unroll
            for (int j = 0; j < 4; j++) {
                float hi, lo; split_tf32(bv[j], hi, lo);
                Bh[br * 128 + bc + j] = hi;
                Bl[br * 128 + bc + j] = lo;
            }
        }
        __syncthreads();

        // prefetch next tile (latency hidden under compute)
        if (k0 + 16 < K) {
#pragma unroll
            for (int v = 0; v < 2; v++) {
                int id4 = tid + v * 256;
                int am = id4 >> 2, ak = (id4 & 3) * 4;
                aReg[v] = *reinterpret_cast<const float4*>(
                    &A[(size_t)(bRow + am) * K + k0 + 16 + ak]);
                int br = id4 >> 5, bc = (id4 & 31) * 4;
                bReg[v] = *reinterpret_cast<const float4*>(
                    &W[(size_t)(k0 + 16 + br) * N + bCol + bc]);
            }
        }

#pragma unroll
        for (int ks = 0; ks < 2; ks++) {
            wmma::fragment<wmma::matrix_a, 16, 16, 8, wmma::precision::tf32, wmma::col_major> ah[4], al[4];
            wmma::fragment<wmma::matrix_b, 16, 16, 8, wmma::precision::tf32, wmma::row_major> bh[2], bl[2];
#pragma unroll
            for (int m = 0; m < 4; m++) {
                wmma::load_matrix_sync(ah[m], &Ah[(ks * 8) * 128 + warp_m * 64 + m * 16], 128);
                wmma::load_matrix_sync(al[m], &Al[(ks * 8) * 128 + warp_m * 64 + m * 16], 128);
            }
#pragma unroll
            for (int n = 0; n < 2; n++) {
                wmma::load_matrix_sync(bh[n], &Bh[(ks * 8) * 128 + warp_n * 32 + n * 16], 128);
                wmma::load_matrix_sync(bl[n], &Bl[(ks * 8) * 128 + warp_n * 32 + n * 16], 128);
            }
#pragma unroll
            for (int m = 0; m < 4; m++)
#pragma unroll
                for (int n = 0; n < 2; n++) {
                    wmma::mma_sync(acc[m][n], ah[m], bh[n], acc[m][n]);
                    wmma::mma_sync(acc[m][n], al[m], bh[n], acc[m][n]);
                    wmma::mma_sync(acc[m][n], ah[m], bl[n], acc[m][n]);
                }
        }
        __syncthreads();
    }

    // Epilogue: via smem scratch (reuse tiles), add bias, vector stores
#pragma unroll
    for (int r = 0; r < 2; r++) {
#pragma unroll
        for (int m = 0; m < 4; m++)
            wmma::store_matrix_sync(&sm[(warp_m * 64 + m * 16) * 64 + warp_n * 16],
                                    acc[m][r], 64, wmma::mem_row_major);
        __syncthreads();
#pragma unroll
        for (int i = 0; i < 8; i++) {
            int id4 = tid + i * 256;                 // 0..2047 float4s
            int srow = id4 >> 4;
            int scol = (id4 & 15) * 4;
            int wn = scol >> 4, cc = scol & 15;
            int gcol = bCol + wn * 32 + r * 16 + cc;
            float4 v = *reinterpret_cast<float4*>(&sm[srow * 64 + scol]);
            float4 bv = *reinterpret_cast<const float4*>(&bias[gcol]);
            v.x += bv.x; v.y += bv.y; v.z += bv.z; v.w += bv.w;
            *reinterpret_cast<float4*>(&C[(size_t)(bRow + srow) * N + gcol]) = v;
        }
        __syncthreads();
    }
}

// ---------------------------------------------------------------------------
// Flash attention, 3xTF32 tensor-core version.
// CTA: 128 q-rows of one (b,h). 64-key tiles. No max-subtraction (scores
// ~N(0,1), exp can't overflow). O accumulates in persistent wmma fragments.
// ---------------------------------------------------------------------------
__global__ __launch_bounds__(256) void attn_kernel(
    const float* __restrict__ Q, const float* __restrict__ K,
    const float* __restrict__ V, float* __restrict__ O)
{
    extern __shared__ float sm[];
    float* Qh = sm;                 // [128][64]
    float* Ql = Qh + 8192;
    float* Kh = Ql + 8192;          // [64][64]
    float* Kl = Kh + 4096;
    float* Vh = Kl + 4096;          // [64][64]
    float* Vl = Vh + 4096;
    float* SP = Vl + 4096;          // [128][64] scores -> P_hi (in place)
    float* Pl = SP + 8192;          // [128][64] P_lo
    float* lrow = Pl + 8192;        // [128]

    const int tid = threadIdx.x;
    const int wid = tid >> 5;
    const int bh = blockIdx.y;
    const int b = bh >> 4, h = bh & 15;
    const int q0 = blockIdx.x * 128;
    const int warp_m = wid & 3;     // q-rows warp_m*32
    const int warp_n = wid >> 2;    // 0..1: key/dh cols warp_n*32

    // Load Q (pre-scaled by 1/sqrt(64)=0.125, exact) with hi/lo split
    const size_t qbase = ((size_t)(b * SS + q0)) * DD + h * DHH;
#pragma unroll
    for (int i = 0; i < 8; i++) {
        int id4 = tid + i * 256;                  // 2048 float4s
        int row = id4 >> 4, col = (id4 & 15) * 4;
        float4 v = *reinterpret_cast<const float4*>(&Q[qbase + (size_t)row * DD + col]);
        float a[4] = {v.x * 0.125f, v.y * 0.125f, v.z * 0.125f, v.w * 0.125f};
#pragma unroll
        for (int j = 0; j < 4; j++) {
            float hi, lo; split_tf32(a[j], hi, lo);
            Qh[row * 64 + col + j] = hi;
            Ql[row * 64 + col + j] = lo;
        }
    }
    if (tid < 128) lrow[tid] = 0.0f;

    wmma::fragment<wmma::accumulator, 16, 16, 8, float> oacc[2][2];
#pragma unroll
    for (int m = 0; m < 2; m++)
#pragma unroll
        for (int n = 0; n < 2; n++) wmma::fill_fragment(oacc[m][n], 0.0f);

    for (int kt = 0; kt < SS / 64; kt++) {
        __syncthreads();
        // Load K,V tile (64x64), split hi/lo
        const size_t kbase = ((size_t)(b * SS + kt * 64)) * DD + h * DHH;
#pragma unroll
        for (int i = 0; i < 4; i++) {
            int id4 = tid + i * 256;               // 1024 float4s
            int row = id4 >> 4, col = (id4 & 15) * 4;
            float4 kv = *reinterpret_cast<const float4*>(&K[kbase + (size_t)row * DD + col]);
            float4 vv = *reinterpret_cast<const float4*>(&V[kbase + (size_t)row * DD + col]);
            float ka[4] = {kv.x, kv.y, kv.z, kv.w};
            float va[4] = {vv.x, vv.y, vv.z, vv.w};
#pragma unroll
            for (int j = 0; j < 4; j++) {
                float hi, lo;
                split_tf32(ka[j], hi, lo);
                Kh[row * 64 + col + j] = hi; Kl[row * 64 + col + j] = lo;
                split_tf32(va[j], hi, lo);
                Vh[row * 64 + col + j] = hi; Vl[row * 64 + col + j] = lo;
            }
        }
        __syncthreads();

        // Scores: S(128x64) = Qs @ K^T   (3xTF32)
        wmma::fragment<wmma::accumulator, 16, 16, 8, float> sacc[2][2];
#pragma unroll
        for (int m = 0; m < 2; m++)
#pragma unroll
            for (int n = 0; n < 2; n++) wmma::fill_fragment(sacc[m][n], 0.0f);
#pragma unroll
        for (int kk = 0; kk < 8; kk++) {
            wmma::fragment<wmma::matrix_a, 16, 16, 8, wmma::precision::tf32, wmma::row_major> qa_h[2], qa_l[2];
            wmma::fragment<wmma::matrix_b, 16, 16, 8, wmma::precision::tf32, wmma::col_major> kb_h[2], kb_l[2];
#pragma unroll
            for (int m = 0; m < 2; m++) {
                wmma::load_matrix_sync(qa_h[m], &Qh[(warp_m * 32 + m * 16) * 64 + kk * 8], 64);
                wmma::load_matrix_sync(qa_l[m], &Ql[(warp_m * 32 + m * 16) * 64 + kk * 8], 64);
            }
#pragma unroll
            for (int n = 0; n < 2; n++) {
                wmma::load_matrix_sync(kb_h[n], &Kh[(warp_n * 32 + n * 16) * 64 + kk * 8], 64);
                wmma::load_matrix_sync(kb_l[n], &Kl[(warp_n * 32 + n * 16) * 64 + kk * 8], 64);
            }
#pragma unroll
            for (int m = 0; m < 2; m++)
#pragma unroll
                for (int n = 0; n < 2; n++) {
                    wmma::mma_sync(sacc[m][n], qa_h[m], kb_h[n], sacc[m][n]);
                    wmma::mma_sync(sacc[m][n], qa_l[m], kb_h[n], sacc[m][n]);
                    wmma::mma_sync(sacc[m][n], qa_h[m], kb_l[n], sacc[m][n]);
                }
        }
#pragma unroll
        for (int m = 0; m < 2; m++)
#pragma unroll
            for (int n = 0; n < 2; n++)
                wmma::store_matrix_sync(&SP[(warp_m * 32 + m * 16) * 64 + warp_n * 32 + n * 16],
                                        sacc[m][n], 64, wmma::mem_row_major);
        __syncthreads();

        // exp (FFMA poly), tf32 split of P, row-sum accumulation
        {
            int row = tid >> 1;
            int cbase = (tid & 1) * 32;
            float* sp = &SP[row * 64 + cbase];
            float* pl = &Pl[row * 64 + cbase];
            float lsum = 0.0f;
#pragma unroll
            for (int j = 0; j < 8; j++) {
                float4 s = *reinterpret_cast<float4*>(&sp[j * 4]);
                float p0 = fexp(s.x), p1 = fexp(s.y), p2 = fexp(s.z), p3 = fexp(s.w);
                lsum += (p0 + p1) + (p2 + p3);
                float4 hi, lo;
                split_tf32(p0, hi.x, lo.x); split_tf32(p1, hi.y, lo.y);
                split_tf32(p2, hi.z, lo.z); split_tf32(p3, hi.w, lo.w);
                *reinterpret_cast<float4*>(&sp[j * 4]) = hi;
                *reinterpret_cast<float4*>(&pl[j * 4]) = lo;
            }
            lsum += __shfl_xor_sync(0xffffffff, lsum, 1);
            if ((tid & 1) == 0) lrow[row] += lsum;
        }
        __syncthreads();

        // O += P @ V  (3xTF32), persistent accumulators
#pragma unroll
        for (int kk = 0; kk < 8; kk++) {
            wmma::fragment<wmma::matrix_a, 16, 16, 8, wmma::precision::tf32, wmma::row_major> pa_h[2], pa_l[2];
            wmma::fragment<wmma::matrix_b, 16, 16, 8, wmma::precision::tf32, wmma::row_major> vb_h[2], vb_l[2];
#pragma unroll
            for (int m = 0; m < 2; m++) {
                wmma::load_matrix_sync(pa_h[m], &SP[(warp_m * 32 + m * 16) * 64 + kk * 8], 64);
                wmma::load_matrix_sync(pa_l[m], &Pl[(warp_m * 32 + m * 16) * 64 + kk * 8], 64);
            }
#pragma unroll
            for (int n = 0; n < 2; n++) {
                wmma::load_matrix_sync(vb_h[n], &Vh[(kk * 8) * 64 + warp_n * 32 + n * 16], 64);
                wmma::load_matrix_sync(vb_l[n], &Vl[(kk * 8) * 64 + warp_n * 32 + n * 16], 64);
            }
#pragma unroll
            for (int m = 0; m < 2; m++)
#pragma unroll
                for (int n = 0; n < 2; n++) {
                    wmma::mma_sync(oacc[m][n], pa_h[m], vb_h[n], oacc[m][n]);
                    wmma::mma_sync(oacc[m][n], pa_l[m], vb_h[n], oacc[m][n]);
                    wmma::mma_sync(oacc[m][n], pa_h[m], vb_l[n], oacc[m][n]);
                }
        }
    }

    __syncthreads();
    // Normalize + write out (via SP scratch)
#pragma unroll
    for (int m = 0; m < 2; m++)
#pragma unroll
        for (int n = 0; n < 2; n++)
            wmma::store_matrix_sync(&SP[(warp_m * 32 + m * 16) * 64 + warp_n * 32 + n * 16],
                                    oacc[m][n], 64, wmma::mem_row_major);
    __syncthreads();
    {
        int row = tid >> 1;
        int cbase = (tid & 1) * 32;
        float inv = 1.0f / lrow[row];
        size_t obase = ((size_t)(b * SS + q0 + row)) * DD + h * DHH + cbase;
#pragma unroll
        for (int j = 0; j < 8; j++) {
            float4 v = *reinterpret_cast<float4*>(&SP[row * 64 + cbase + j * 4]);
            v.x *= inv; v.y *= inv; v.z *= inv; v.w *= inv;
            *reinterpret_cast<float4*>(&O[obase + j * 4]) = v;
        }
    }
}

// ---------------------------------------------------------------------------
extern "C" void kernel_launch(void* const* d_in, const int* in_sizes, int n_in,
                              void* d_out, int out_size)
{
    const float* x  = (const float*)d_in[0];
    const float* Wq = (const float*)d_in[1];
    const float* bq = (const float*)d_in[2];
    const float* Wk = (const float*)d_in[3];
    const float* bk = (const float*)d_in[4];
    const float* Wv = (const float*)d_in[5];
    const float* bv = (const float*)d_in[6];
    const float* Wo = (const float*)d_in[7];
    const float* bo = (const float*)d_in[8];
    float* out = (float*)d_out;

    float *Q, *K, *V, *AO;
    cudaGetSymbolAddress((void**)&Q,  g_Q);
    cudaGetSymbolAddress((void**)&K,  g_K);
    cudaGetSymbolAddress((void**)&V,  g_V);
    cudaGetSymbolAddress((void**)&AO, g_AO);

    static const size_t ATTN_SMEM = 49280 * sizeof(float);   // 192.5 KB
    cudaFuncSetAttribute(attn_kernel, cudaFuncAttributeMaxDynamicSharedMemorySize,
                         (int)ATTN_SMEM);

    // Fused QKV projection (3 weight matrices, one launch, 768 CTAs)
    gemm3_kernel<<<dim3(24, 32), 256>>>(x, Wq, Wk, Wv, bq, bk, bv, Q, K, V);

    // Attention
    attn_kernel<<<dim3(SS / 128, BB * HH), 256, ATTN_SMEM>>>(Q, K, V, AO);

    // Output projection
    gemm3_kernel<<<dim3(8, 32), 256>>>(AO, Wo, Wo, Wo, bo, bo, bo, out, out, out);
}

// round 5
// speedup vs baseline: 1.7875x; 1.7875x over previous
#include <cuda_runtime.h>
#include <cuda_bf16.h>
#include <cstdint>
#include <math.h>

#define BB 2
#define SS 2048
#define DD 1024
#define HH 16
#define DHH 64
#define MM (BB * SS)

// Scratch (allocation-free rule -> device globals)
__device__ float g_Q[(size_t)BB * SS * DD];
__device__ float g_K[(size_t)BB * SS * DD];
__device__ float g_V[(size_t)BB * SS * DD];
__device__ float g_AO[(size_t)BB * SS * DD];

__device__ __forceinline__ uint32_t smem_to_u32(const void* p) {
    uint32_t a;
    asm("{ .reg .u64 t; cvta.to.shared.u64 t, %1; cvt.u32.u64 %0, t; }"
        : "=r"(a) : "l"(p));
    return a;
}

__device__ __forceinline__ void ldsm4(uint32_t addr, uint32_t& r0, uint32_t& r1,
                                      uint32_t& r2, uint32_t& r3) {
    asm volatile("ldmatrix.sync.aligned.m8n8.x4.shared.b16 {%0,%1,%2,%3}, [%4];"
                 : "=r"(r0), "=r"(r1), "=r"(r2), "=r"(r3) : "r"(addr));
}

__device__ __forceinline__ void mma_bf16(float* d, const uint32_t* a, const uint32_t* b) {
    asm volatile(
        "mma.sync.aligned.m16n8k16.row.col.f32.bf16.bf16.f32 "
        "{%0,%1,%2,%3}, {%4,%5,%6,%7}, {%8,%9}, {%0,%1,%2,%3};"
        : "+f"(d[0]), "+f"(d[1]), "+f"(d[2]), "+f"(d[3])
        : "r"(a[0]), "r"(a[1]), "r"(a[2]), "r"(a[3]), "r"(b[0]), "r"(b[1]));
}

__device__ __forceinline__ void bf_split(float x, __nv_bfloat16& h, __nv_bfloat16& l) {
    h = __float2bfloat16(x);
    l = __float2bfloat16(x - __bfloat162float(h));
}
__device__ __forceinline__ uint32_t pack_bf(__nv_bfloat16 a, __nv_bfloat16 b) {
    __nv_bfloat162 t(a, b);
    return *reinterpret_cast<uint32_t*>(&t);
}

// Swizzled byte offset in a [128 rows][32 bf16] tile (64B rows, 4x16B chunks).
// chunk' = chunk ^ ((row>>1)&3): conflict-free for ldmatrix 8-row groups.
__device__ __forceinline__ uint32_t swz(int row, int chunk) {
    return (uint32_t)(row * 64 + ((chunk ^ ((row >> 1) & 3)) << 4));
}

// ===========================================================================
// bf16x3 GEMM via mma.sync: C[M,1024] = A[M,1024] @ W + bias.
// 3 weight sets per launch (which = blockIdx.x>>3). CTA tile 128x128, BK=32,
// 256 threads = 8 warps (4M x 2N), warp tile 32x64, double-buffered smem.
// ===========================================================================
#define AHI 0
#define ALO 8192
#define BHI 16384
#define BLO 24576
#define STG 32768
#define GEMM_SMEM (2 * STG)
#define NCHUNK 32

__global__ __launch_bounds__(256) void gemm_tc(
    const float* __restrict__ A,
    const float* __restrict__ W0, const float* __restrict__ W1, const float* __restrict__ W2,
    const float* __restrict__ b0, const float* __restrict__ b1, const float* __restrict__ b2,
    float* __restrict__ C0, float* __restrict__ C1, float* __restrict__ C2)
{
    extern __shared__ char smem[];
    const uint32_t sbase = smem_to_u32(smem);
    const int tid = threadIdx.x;
    const int wid = tid >> 5;
    const int lane = tid & 31;

    const int which = blockIdx.x >> 3;
    const float* W    = (which == 0) ? W0 : (which == 1) ? W1 : W2;
    const float* bias = (which == 0) ? b0 : (which == 1) ? b1 : b2;
    float*       C    = (which == 0) ? C0 : (which == 1) ? C1 : C2;
    const int bCol = (blockIdx.x & 7) * 128;
    const int bRow = blockIdx.y * 128;

    const int warpM = (wid >> 1) * 32;   // 0,32,64,96
    const int warpN = (wid & 1) * 64;    // 0,64

    // ldmatrix per-lane geometry
    const int sub = lane >> 3;           // matrix index 0..3
    const int li  = lane & 7;
    // A frags (fm=0,1): matrices: {rows+0..7,k0},{rows+8..15,k0},{rows,k1},{rows+8,k1}
    int rA[2]; uint32_t baseA[2]; int swA[2];
#pragma unroll
    for (int fm = 0; fm < 2; fm++) {
        rA[fm] = warpM + fm * 16 + (sub & 1) * 8 + li;
        baseA[fm] = (uint32_t)(rA[fm] * 64);
        swA[fm] = (rA[fm] >> 1) & 3;
    }
    const int chA_off = sub >> 1;        // +0 or +1 chunk
    // B frags (nb=0..3, each = n16 pair): matrices {n0..7,k0},{n0..7,k1},{n8..15,k0},{n8..15,k1}
    int rB[4]; uint32_t baseB[4]; int swB[4];
#pragma unroll
    for (int nb = 0; nb < 4; nb++) {
        rB[nb] = warpN + nb * 16 + ((sub >> 1) & 1) * 8 + li;
        baseB[nb] = (uint32_t)(rB[nb] * 64);
        swB[nb] = (rB[nb] >> 1) & 3;
    }
    const int chB_off = sub & 1;

    float acc[2][8][4];
#pragma unroll
    for (int fm = 0; fm < 2; fm++)
#pragma unroll
        for (int fn = 0; fn < 8; fn++)
#pragma unroll
            for (int r = 0; r < 4; r++) acc[fm][fn][r] = 0.0f;

    // global load mappings
    const int aRow0 = tid >> 3;              // + v*32
    const int aC4   = (tid & 7) * 4;
    const int bK0   = tid >> 5;              // + v*8
    const int bN4   = (tid & 31) * 4;

    float4 aPre[4], bPre[4];
#pragma unroll
    for (int v = 0; v < 4; v++) {
        aPre[v] = *reinterpret_cast<const float4*>(
            &A[(size_t)(bRow + aRow0 + v * 32) * DD + aC4]);
        bPre[v] = *reinterpret_cast<const float4*>(
            &W[(size_t)(bK0 + v * 8) * DD + bCol + bN4]);
    }

    // store chunk 0 into stage 0
    {
        char* sb = smem;
#pragma unroll
        for (int v = 0; v < 4; v++) {
            int row = aRow0 + v * 32;
            float x[4] = {aPre[v].x, aPre[v].y, aPre[v].z, aPre[v].w};
            __nv_bfloat16 h[4], l[4];
#pragma unroll
            for (int j = 0; j < 4; j++) bf_split(x[j], h[j], l[j]);
            uint32_t off = swz(row, aC4 >> 3) + (aC4 & 7) * 2;
            *reinterpret_cast<uint2*>(sb + AHI + off) = make_uint2(pack_bf(h[0], h[1]), pack_bf(h[2], h[3]));
            *reinterpret_cast<uint2*>(sb + ALO + off) = make_uint2(pack_bf(l[0], l[1]), pack_bf(l[2], l[3]));
            int k = bK0 + v * 8;
            float y[4] = {bPre[v].x, bPre[v].y, bPre[v].z, bPre[v].w};
#pragma unroll
            for (int j = 0; j < 4; j++) {
                __nv_bfloat16 hh, ll; bf_split(y[j], hh, ll);
                uint32_t o2 = swz(bN4 + j, k >> 3) + (k & 7) * 2;
                *reinterpret_cast<__nv_bfloat16*>(sb + BHI + o2) = hh;
                *reinterpret_cast<__nv_bfloat16*>(sb + BLO + o2) = ll;
            }
        }
    }
    __syncthreads();

    for (int c = 0; c < NCHUNK; c++) {
        const int cur = c & 1;
        // prefetch next chunk
        if (c + 1 < NCHUNK) {
#pragma unroll
            for (int v = 0; v < 4; v++) {
                aPre[v] = *reinterpret_cast<const float4*>(
                    &A[(size_t)(bRow + aRow0 + v * 32) * DD + (c + 1) * 32 + aC4]);
                bPre[v] = *reinterpret_cast<const float4*>(
                    &W[(size_t)((c + 1) * 32 + bK0 + v * 8) * DD + bCol + bN4]);
            }
        }

        // mma on stage cur
        const uint32_t st = sbase + cur * STG;
#pragma unroll
        for (int ks = 0; ks < 2; ks++) {
            uint32_t ah[2][4], al[2][4];
#pragma unroll
            for (int fm = 0; fm < 2; fm++) {
                uint32_t chunk = (uint32_t)((2 * ks + chA_off) ^ swA[fm]) << 4;
                ldsm4(st + AHI + baseA[fm] + chunk, ah[fm][0], ah[fm][1], ah[fm][2], ah[fm][3]);
                ldsm4(st + ALO + baseA[fm] + chunk, al[fm][0], al[fm][1], al[fm][2], al[fm][3]);
            }
            uint32_t bh[4][4], bl[4][4];
#pragma unroll
            for (int nb = 0; nb < 4; nb++) {
                uint32_t chunk = (uint32_t)((2 * ks + chB_off) ^ swB[nb]) << 4;
                ldsm4(st + BHI + baseB[nb] + chunk, bh[nb][0], bh[nb][1], bh[nb][2], bh[nb][3]);
                ldsm4(st + BLO + baseB[nb] + chunk, bl[nb][0], bl[nb][1], bl[nb][2], bl[nb][3]);
            }
#pragma unroll
            for (int fm = 0; fm < 2; fm++)
#pragma unroll
                for (int nb = 0; nb < 4; nb++)
#pragma unroll
                    for (int hf = 0; hf < 2; hf++) {
                        float* d = acc[fm][nb * 2 + hf];
                        mma_bf16(d, ah[fm], &bh[nb][hf * 2]);   // hi*hi
                        mma_bf16(d, al[fm], &bh[nb][hf * 2]);   // lo*hi
                        mma_bf16(d, ah[fm], &bl[nb][hf * 2]);   // hi*lo
                    }
        }

        // store prefetched chunk into other stage
        if (c + 1 < NCHUNK) {
            char* sb = smem + (cur ^ 1) * STG;
#pragma unroll
            for (int v = 0; v < 4; v++) {
                int row = aRow0 + v * 32;
                float x[4] = {aPre[v].x, aPre[v].y, aPre[v].z, aPre[v].w};
                __nv_bfloat16 h[4], l[4];
#pragma unroll
                for (int j = 0; j < 4; j++) bf_split(x[j], h[j], l[j]);
                uint32_t off = swz(row, aC4 >> 3) + (aC4 & 7) * 2;
                *reinterpret_cast<uint2*>(sb + AHI + off) = make_uint2(pack_bf(h[0], h[1]), pack_bf(h[2], h[3]));
                *reinterpret_cast<uint2*>(sb + ALO + off) = make_uint2(pack_bf(l[0], l[1]), pack_bf(l[2], l[3]));
                int k = bK0 + v * 8;
                float y[4] = {bPre[v].x, bPre[v].y, bPre[v].z, bPre[v].w};
#pragma unroll
                for (int j = 0; j < 4; j++) {
                    __nv_bfloat16 hh, ll; bf_split(y[j], hh, ll);
                    uint32_t o2 = swz(bN4 + j, k >> 3) + (k & 7) * 2;
                    *reinterpret_cast<__nv_bfloat16*>(sb + BHI + o2) = hh;
                    *reinterpret_cast<__nv_bfloat16*>(sb + BLO + o2) = ll;
                }
            }
        }
        __syncthreads();
    }

    // Epilogue: fragment layout -> global, add bias
#pragma unroll
    for (int fm = 0; fm < 2; fm++) {
        int row0 = bRow + warpM + fm * 16 + (lane >> 2);
#pragma unroll
        for (int fn = 0; fn < 8; fn++) {
            int col = bCol + warpN + fn * 8 + 2 * (lane & 3);
            float bx = bias[col], by = bias[col + 1];
            float2 v0 = {acc[fm][fn][0] + bx, acc[fm][fn][1] + by};
            float2 v1 = {acc[fm][fn][2] + bx, acc[fm][fn][3] + by};
            *reinterpret_cast<float2*>(&C[(size_t)row0 * DD + col]) = v0;
            *reinterpret_cast<float2*>(&C[(size_t)(row0 + 8) * DD + col]) = v1;
        }
    }
}

// ===========================================================================
// Flash attention (SIMT, fused, no online max): thread-per-query-row.
// 4-way split score accumulation breaks the serial FFMA chain.
// ===========================================================================
#define BQ 128
#define BKT 32

__global__ __launch_bounds__(128) void attn_kernel(
    const float* __restrict__ Q, const float* __restrict__ K,
    const float* __restrict__ V, float* __restrict__ O)
{
    __shared__ float k_sh[BKT][DHH];
    __shared__ float v_sh[BKT][DHH];

    const int tid = threadIdx.x;
    const int bh = blockIdx.y;
    const int b = bh >> 4, h = bh & 15;
    const int qs = blockIdx.x * BQ + tid;

    float q[DHH];
    {
        const float* qp = Q + (size_t)(b * SS + qs) * DD + h * DHH;
#pragma unroll
        for (int d4 = 0; d4 < DHH / 4; d4++) {
            float4 t = *reinterpret_cast<const float4*>(&qp[d4 * 4]);
            q[d4 * 4 + 0] = t.x * 0.125f;
            q[d4 * 4 + 1] = t.y * 0.125f;
            q[d4 * 4 + 2] = t.z * 0.125f;
            q[d4 * 4 + 3] = t.w * 0.125f;
        }
    }

    float o[DHH];
#pragma unroll
    for (int d = 0; d < DHH; d++) o[d] = 0.0f;
    float l = 0.0f;

    for (int kt = 0; kt < SS / BKT; kt++) {
        __syncthreads();
        const size_t base = (size_t)(b * SS + kt * BKT) * DD + h * DHH;
#pragma unroll
        for (int i = 0; i < 4; i++) {
            int e = tid + i * 128;
            int kr = e >> 4;
            int d4 = (e & 15) * 4;
            *reinterpret_cast<float4*>(&k_sh[kr][d4]) =
                *reinterpret_cast<const float4*>(&K[base + (size_t)kr * DD + d4]);
            *reinterpret_cast<float4*>(&v_sh[kr][d4]) =
                *reinterpret_cast<const float4*>(&V[base + (size_t)kr * DD + d4]);
        }
        __syncthreads();

#pragma unroll 4
        for (int kc = 0; kc < BKT; kc++) {
            const float4* kv = reinterpret_cast<const float4*>(k_sh[kc]);
            float s0 = 0.f, s1 = 0.f, s2 = 0.f, s3 = 0.f;
#pragma unroll
            for (int d4 = 0; d4 < DHH / 4; d4++) {
                float4 t = kv[d4];
                s0 = fmaf(q[d4 * 4 + 0], t.x, s0);
                s1 = fmaf(q[d4 * 4 + 1], t.y, s1);
                s2 = fmaf(q[d4 * 4 + 2], t.z, s2);
                s3 = fmaf(q[d4 * 4 + 3], t.w, s3);
            }
            float p = __expf((s0 + s1) + (s2 + s3));
            l += p;
            const float4* vv = reinterpret_cast<const float4*>(v_sh[kc]);
#pragma unroll
            for (int d4 = 0; d4 < DHH / 4; d4++) {
                float4 t = vv[d4];
                o[d4 * 4 + 0] = fmaf(p, t.x, o[d4 * 4 + 0]);
                o[d4 * 4 + 1] = fmaf(p, t.y, o[d4 * 4 + 1]);
                o[d4 * 4 + 2] = fmaf(p, t.z, o[d4 * 4 + 2]);
                o[d4 * 4 + 3] = fmaf(p, t.w, o[d4 * 4 + 3]);
            }
        }
    }

    const float inv = 1.0f / l;
    float* op = O + (size_t)(b * SS + qs) * DD + h * DHH;
#pragma unroll
    for (int d4 = 0; d4 < DHH / 4; d4++) {
        float4 t;
        t.x = o[d4 * 4 + 0] * inv;
        t.y = o[d4 * 4 + 1] * inv;
        t.z = o[d4 * 4 + 2] * inv;
        t.w = o[d4 * 4 + 3] * inv;
        *reinterpret_cast<float4*>(&op[d4 * 4]) = t;
    }
}

// ===========================================================================
extern "C" void kernel_launch(void* const* d_in, const int* in_sizes, int n_in,
                              void* d_out, int out_size)
{
    const float* x  = (const float*)d_in[0];
    const float* Wq = (const float*)d_in[1];
    const float* bq = (const float*)d_in[2];
    const float* Wk = (const float*)d_in[3];
    const float* bk = (const float*)d_in[4];
    const float* Wv = (const float*)d_in[5];
    const float* bv = (const float*)d_in[6];
    const float* Wo = (const float*)d_in[7];
    const float* bo = (const float*)d_in[8];
    float* out = (float*)d_out;

    float *Q, *K, *V, *AO;
    cudaGetSymbolAddress((void**)&Q,  g_Q);
    cudaGetSymbolAddress((void**)&K,  g_K);
    cudaGetSymbolAddress((void**)&V,  g_V);
    cudaGetSymbolAddress((void**)&AO, g_AO);

    cudaFuncSetAttribute(gemm_tc, cudaFuncAttributeMaxDynamicSharedMemorySize, GEMM_SMEM);

    // QKV projections (which = blockIdx.x>>3)
    gemm_tc<<<dim3(24, 32), 256, GEMM_SMEM>>>(x, Wq, Wk, Wv, bq, bk, bv, Q, K, V);

    // Attention
    attn_kernel<<<dim3(SS / BQ, BB * HH), 128>>>(Q, K, V, AO);

    // Output projection
    gemm_tc<<<dim3(8, 32), 256, GEMM_SMEM>>>(AO, Wo, Wo, Wo, bo, bo, bo, out, out, out);
}

// round 8
// speedup vs baseline: 11.2171x; 6.2751x over previous
#include <cuda_runtime.h>
#include <cuda_bf16.h>
#include <cstdint>
#include <math.h>

#define BB 2
#define SS 2048
#define DD 1024
#define HH 16
#define DHH 64
#define MM (BB * SS)

// ---------------- scratch (device globals: allocation-free rule) -----------
__device__ __nv_bfloat16 g_xh[(size_t)MM * DD], g_xl[(size_t)MM * DD];
__device__ __nv_bfloat16 g_Wth[(size_t)4 * DD * DD], g_Wtl[(size_t)4 * DD * DD];
__device__ __nv_bfloat16 g_Qh[(size_t)MM * DD], g_Ql[(size_t)MM * DD];
__device__ __nv_bfloat16 g_Kh[(size_t)MM * DD], g_Kl[(size_t)MM * DD];
__device__ __nv_bfloat16 g_Vth[(size_t)MM * DD], g_Vtl[(size_t)MM * DD];  // [B][D][S]
__device__ __nv_bfloat16 g_AOh[(size_t)MM * DD], g_AOl[(size_t)MM * DD];

// ---------------- helpers --------------------------------------------------
__device__ __forceinline__ uint32_t smem_to_u32(const void* p) {
    uint32_t a;
    asm("{ .reg .u64 t; cvta.to.shared.u64 t, %1; cvt.u32.u64 %0, t; }"
        : "=r"(a) : "l"(p));
    return a;
}
__device__ __forceinline__ void ldsm4(uint32_t addr, uint32_t& r0, uint32_t& r1,
                                      uint32_t& r2, uint32_t& r3) {
    asm volatile("ldmatrix.sync.aligned.m8n8.x4.shared.b16 {%0,%1,%2,%3}, [%4];"
                 : "=r"(r0), "=r"(r1), "=r"(r2), "=r"(r3) : "r"(addr));
}
__device__ __forceinline__ void mma_bf16(float* d, const uint32_t* a, const uint32_t* b) {
    asm volatile(
        "mma.sync.aligned.m16n8k16.row.col.f32.bf16.bf16.f32 "
        "{%0,%1,%2,%3}, {%4,%5,%6,%7}, {%8,%9}, {%0,%1,%2,%3};"
        : "+f"(d[0]), "+f"(d[1]), "+f"(d[2]), "+f"(d[3])
        : "r"(a[0]), "r"(a[1]), "r"(a[2]), "r"(a[3]), "r"(b[0]), "r"(b[1]));
}
__device__ __forceinline__ void bf_split(float x, __nv_bfloat16& h, __nv_bfloat16& l) {
    h = __float2bfloat16(x);
    l = __float2bfloat16(x - __bfloat162float(h));
}
__device__ __forceinline__ uint32_t pack_bf(__nv_bfloat16 a, __nv_bfloat16 b) {
    __nv_bfloat162 t(a, b);
    return *reinterpret_cast<uint32_t*>(&t);
}
#define CPA16(dst, src) \
    asm volatile("cp.async.cg.shared.global [%0], [%1], 16;" :: "r"(dst), "l"(src))
#define CPCOMMIT() asm volatile("cp.async.commit_group;" ::: "memory")
#define CPWAIT(n)  asm volatile("cp.async.wait_group %0;" :: "n"(n) : "memory")

// swizzle for [rows][32 bf16] tiles (64B rows, 4x16B chunks)
__device__ __forceinline__ uint32_t swz(int row, int chunk) {
    return (uint32_t)(row * 64 + ((chunk ^ ((row >> 1) & 3)) << 4));
}
// swizzle for [rows][64 bf16] tiles (128B rows, 8x16B chunks)
__device__ __forceinline__ uint32_t sw8(int row, int c8) {
    return (uint32_t)(row * 128 + ((c8 ^ (row & 7)) << 4));
}

// ---------------- conversion kernels ---------------------------------------
__global__ __launch_bounds__(256) void conv_split(
    const float* __restrict__ X, __nv_bfloat16* __restrict__ H,
    __nv_bfloat16* __restrict__ L, int n4)
{
    int i = blockIdx.x * 256 + threadIdx.x;
    if (i >= n4) return;
    float4 v = reinterpret_cast<const float4*>(X)[i];
    __nv_bfloat16 h0, l0, h1, l1, h2, l2, h3, l3;
    bf_split(v.x, h0, l0); bf_split(v.y, h1, l1);
    bf_split(v.z, h2, l2); bf_split(v.w, h3, l3);
    reinterpret_cast<uint2*>(H)[i] = make_uint2(pack_bf(h0, h1), pack_bf(h2, h3));
    reinterpret_cast<uint2*>(L)[i] = make_uint2(pack_bf(l0, l1), pack_bf(l2, l3));
}

__global__ __launch_bounds__(256) void conv_wt(
    const float* __restrict__ W0, const float* __restrict__ W1,
    const float* __restrict__ W2, const float* __restrict__ W3,
    __nv_bfloat16* __restrict__ H, __nv_bfloat16* __restrict__ L)
{
    __shared__ float t[32][33];
    const int mat = blockIdx.z;
    const float* W = (mat == 0) ? W0 : (mat == 1) ? W1 : (mat == 2) ? W2 : W3;
    const int r0 = blockIdx.y * 32, c0 = blockIdx.x * 32;
    const int tx = threadIdx.x & 31, ty = threadIdx.x >> 5;
#pragma unroll
    for (int j = 0; j < 4; j++)
        t[ty + j * 8][tx] = W[(size_t)(r0 + ty + j * 8) * DD + c0 + tx];
    __syncthreads();
#pragma unroll
    for (int j = 0; j < 4; j++) {
        float v = t[tx][ty + j * 8];
        __nv_bfloat16 h, l; bf_split(v, h, l);
        size_t dst = (size_t)mat * DD * DD + (size_t)(c0 + ty + j * 8) * DD + r0 + tx;
        H[dst] = h; L[dst] = l;
    }
}

// ===========================================================================
// bf16x3 GEMM with pre-converted inputs + cp.async 4-stage pipeline.
// A: hi/lo bf16 [M][1024]. Bt: hi/lo bf16 [n][k] (pre-transposed).
// nmats=3: m = bx>>3 selects Bt slice + output (m<2: split hi/lo, m==2:
// transposed split -> Vt). nmats=1: fp32 output Cf.
// CTA tile 128x128, BK=32, 8 warps (4Mx2N), warp tile 32x64.
// ===========================================================================
#define STG2 32768
#define GEMM_SMEM (4 * STG2)
#define NCHUNK 32

__global__ __launch_bounds__(256) void gemm_bf3(
    const __nv_bfloat16* __restrict__ Ah, const __nv_bfloat16* __restrict__ Al,
    const __nv_bfloat16* __restrict__ Bth, const __nv_bfloat16* __restrict__ Btl,
    const float* __restrict__ bias0, const float* __restrict__ bias1,
    const float* __restrict__ bias2,
    __nv_bfloat16* __restrict__ C0h, __nv_bfloat16* __restrict__ C0l,
    __nv_bfloat16* __restrict__ C1h, __nv_bfloat16* __restrict__ C1l,
    __nv_bfloat16* __restrict__ C2h, __nv_bfloat16* __restrict__ C2l,
    float* __restrict__ Cf, int nmats)
{
    extern __shared__ char smem[];
    const uint32_t sbase = smem_to_u32(smem);
    const int tid = threadIdx.x;
    const int wid = tid >> 5;
    const int lane = tid & 31;

    const int m = (nmats == 3) ? (int)(blockIdx.x >> 3) : 0;
    const __nv_bfloat16* Bh_g = Bth + (size_t)m * DD * DD;
    const __nv_bfloat16* Bl_g = Btl + (size_t)m * DD * DD;
    const float* bias = (m == 0) ? bias0 : (m == 1) ? bias1 : bias2;
    const int bCol = (blockIdx.x & 7) * 128;
    const int bRow = blockIdx.y * 128;

    const int warpM = (wid >> 1) * 32;
    const int warpN = (wid & 1) * 64;
    const int sub = lane >> 3;
    const int li = lane & 7;

    int rA[2]; uint32_t baseA[2]; int swA[2];
#pragma unroll
    for (int fm = 0; fm < 2; fm++) {
        rA[fm] = warpM + fm * 16 + (sub & 1) * 8 + li;
        baseA[fm] = (uint32_t)(rA[fm] * 64);
        swA[fm] = (rA[fm] >> 1) & 3;
    }
    const int chA_off = sub >> 1;
    int rB[4]; uint32_t baseB[4]; int swB[4];
#pragma unroll
    for (int nb = 0; nb < 4; nb++) {
        rB[nb] = warpN + nb * 16 + ((sub >> 1) & 1) * 8 + li;
        baseB[nb] = (uint32_t)(rB[nb] * 64);
        swB[nb] = (rB[nb] >> 1) & 3;
    }
    const int chB_off = sub & 1;

    float acc[2][8][4];
#pragma unroll
    for (int fm = 0; fm < 2; fm++)
#pragma unroll
        for (int fn = 0; fn < 8; fn++)
#pragma unroll
            for (int r = 0; r < 4; r++) acc[fm][fn][r] = 0.0f;

    // stage fill: 4 arrays x 512 16B-chunks; 256 threads x 2 per array
#define LOAD_STAGE(s, c) do { \
        uint32_t st_ = sbase + (uint32_t)(s) * STG2; \
        _Pragma("unroll") \
        for (int p = 0; p < 2; p++) { \
            int id = tid + p * 256; \
            int row = id >> 2, c4 = id & 3; \
            size_t ga = (size_t)(bRow + row) * DD + (c) * 32 + c4 * 8; \
            uint32_t da = st_ + swz(row, c4); \
            CPA16(da, Ah + ga); \
            CPA16(da + 8192, Al + ga); \
            size_t gb = (size_t)(bCol + row) * DD + (c) * 32 + c4 * 8; \
            uint32_t db = st_ + 16384 + swz(row, c4); \
            CPA16(db, Bh_g + gb); \
            CPA16(db + 8192, Bl_g + gb); \
        } \
    } while (0)

    LOAD_STAGE(0, 0); CPCOMMIT();
    LOAD_STAGE(1, 1); CPCOMMIT();
    LOAD_STAGE(2, 2); CPCOMMIT();

    for (int c = 0; c < NCHUNK; c++) {
        if (c < 30) { CPWAIT(2); }
        else if (c == 30) { CPWAIT(1); }
        else { CPWAIT(0); }
        __syncthreads();
        if (c + 3 < NCHUNK) { LOAD_STAGE((c + 3) & 3, c + 3); CPCOMMIT(); }

        const uint32_t st = sbase + (uint32_t)(c & 3) * STG2;
#pragma unroll
        for (int ks = 0; ks < 2; ks++) {
            uint32_t ah[2][4], al[2][4];
#pragma unroll
            for (int fm = 0; fm < 2; fm++) {
                uint32_t chunk = (uint32_t)((2 * ks + chA_off) ^ swA[fm]) << 4;
                ldsm4(st + baseA[fm] + chunk, ah[fm][0], ah[fm][1], ah[fm][2], ah[fm][3]);
                ldsm4(st + 8192 + baseA[fm] + chunk, al[fm][0], al[fm][1], al[fm][2], al[fm][3]);
            }
            uint32_t bh[4][4], bl[4][4];
#pragma unroll
            for (int nb = 0; nb < 4; nb++) {
                uint32_t chunk = (uint32_t)((2 * ks + chB_off) ^ swB[nb]) << 4;
                ldsm4(st + 16384 + baseB[nb] + chunk, bh[nb][0], bh[nb][1], bh[nb][2], bh[nb][3]);
                ldsm4(st + 24576 + baseB[nb] + chunk, bl[nb][0], bl[nb][1], bl[nb][2], bl[nb][3]);
            }
#pragma unroll
            for (int fm = 0; fm < 2; fm++)
#pragma unroll
                for (int nb = 0; nb < 4; nb++)
#pragma unroll
                    for (int hf = 0; hf < 2; hf++) {
                        float* d = acc[fm][nb * 2 + hf];
                        mma_bf16(d, ah[fm], &bh[nb][hf * 2]);
                        mma_bf16(d, al[fm], &bh[nb][hf * 2]);
                        mma_bf16(d, ah[fm], &bl[nb][hf * 2]);
                    }
        }
    }
#undef LOAD_STAGE

    // epilogue
    __nv_bfloat16* Ch = (m == 0) ? C0h : (m == 1) ? C1h : C2h;
    __nv_bfloat16* Cl = (m == 0) ? C0l : (m == 1) ? C1l : C2l;
#pragma unroll
    for (int fm = 0; fm < 2; fm++) {
        int row0 = bRow + warpM + fm * 16 + (lane >> 2);
#pragma unroll
        for (int fn = 0; fn < 8; fn++) {
            int col = bCol + warpN + fn * 8 + 2 * (lane & 3);
            float bx = bias[col], by = bias[col + 1];
            float v[4] = {acc[fm][fn][0] + bx, acc[fm][fn][1] + by,
                          acc[fm][fn][2] + bx, acc[fm][fn][3] + by};
            if (nmats == 1) {
                *reinterpret_cast<float2*>(&Cf[(size_t)row0 * DD + col]) =
                    make_float2(v[0], v[1]);
                *reinterpret_cast<float2*>(&Cf[(size_t)(row0 + 8) * DD + col]) =
                    make_float2(v[2], v[3]);
            } else if (m < 2) {
                __nv_bfloat16 h[4], l[4];
#pragma unroll
                for (int j = 0; j < 4; j++) bf_split(v[j], h[j], l[j]);
                *reinterpret_cast<uint32_t*>(&Ch[(size_t)row0 * DD + col]) = pack_bf(h[0], h[1]);
                *reinterpret_cast<uint32_t*>(&Cl[(size_t)row0 * DD + col]) = pack_bf(l[0], l[1]);
                *reinterpret_cast<uint32_t*>(&Ch[(size_t)(row0 + 8) * DD + col]) = pack_bf(h[2], h[3]);
                *reinterpret_cast<uint32_t*>(&Cl[(size_t)(row0 + 8) * DD + col]) = pack_bf(l[2], l[3]);
            } else {
                // transposed: Vt[b][d][s]
#pragma unroll
                for (int j = 0; j < 4; j++) {
                    int r = row0 + (j >> 1) * 8;
                    int cc = col + (j & 1);
                    size_t idx = ((size_t)(r >> 11) * DD + cc) * SS + (r & (SS - 1));
                    __nv_bfloat16 h, l; bf_split(v[j], h, l);
                    Ch[idx] = h; Cl[idx] = l;
                }
            }
        }
    }
}

// ===========================================================================
// Tensor-core flash attention (bf16x3). CTA = 128 q rows of one (b,h);
// 8 warps x 16 rows. Key tiles of 64, 3-stage cp.async. No max-subtraction.
// P repacked register-resident from S accumulators.
// ===========================================================================
#define AT_STG 32768          // Kh 0 | Kl 8192 | Vh 16384 | Vl 24576
#define AT_Q   (3 * AT_STG)   // Qh | Ql (16KB each)
#define ATTN_SMEM (3 * AT_STG + 32768)
#define NKT 32

__global__ __launch_bounds__(256) void attn_tc(
    const __nv_bfloat16* __restrict__ Qh_g, const __nv_bfloat16* __restrict__ Ql_g,
    const __nv_bfloat16* __restrict__ Kh_g, const __nv_bfloat16* __restrict__ Kl_g,
    const __nv_bfloat16* __restrict__ Vth_g, const __nv_bfloat16* __restrict__ Vtl_g,
    __nv_bfloat16* __restrict__ AOh, __nv_bfloat16* __restrict__ AOl)
{
    extern __shared__ char smem[];
    const uint32_t sb = smem_to_u32(smem);
    const int tid = threadIdx.x;
    const int wid = tid >> 5;
    const int lane = tid & 31;
    const int sub = lane >> 3;
    const int li = lane & 7;
    const int bh = blockIdx.y;
    const int b = bh >> 4, h = bh & 15;
    const int q0 = blockIdx.x * 128;

    // Q tile: [128][64] hi/lo
#pragma unroll
    for (int p = 0; p < 4; p++) {
        int id = tid + p * 256;            // 0..1023
        int row = id >> 3, c8 = id & 7;
        size_t src = (size_t)(b * SS + q0 + row) * DD + h * DHH + c8 * 8;
        CPA16(sb + AT_Q + sw8(row, c8), Qh_g + src);
        CPA16(sb + AT_Q + 16384 + sw8(row, c8), Ql_g + src);
    }
    CPCOMMIT();

#define LOAD_KV(s, kt) do { \
        uint32_t st_ = sb + (uint32_t)(s) * AT_STG; \
        _Pragma("unroll") \
        for (int p = 0; p < 2; p++) { \
            int id = tid + p * 256; \
            int row = id >> 3, c8 = id & 7; \
            size_t ks_ = (size_t)(b * SS + (kt) * 64 + row) * DD + h * DHH + c8 * 8; \
            CPA16(st_ + sw8(row, c8), Kh_g + ks_); \
            CPA16(st_ + 8192 + sw8(row, c8), Kl_g + ks_); \
            size_t vs_ = (size_t)(b * DD + h * DHH + row) * SS + (kt) * 64 + c8 * 8; \
            CPA16(st_ + 16384 + sw8(row, c8), Vth_g + vs_); \
            CPA16(st_ + 24576 + sw8(row, c8), Vtl_g + vs_); \
        } \
    } while (0)

    LOAD_KV(0, 0); CPCOMMIT();
    LOAD_KV(1, 1); CPCOMMIT();

    CPWAIT(2);          // Q done
    __syncthreads();

    // Q fragments for all 4 k-chunks (d=64), hi+lo
    uint32_t qh[4][4], ql[4][4];
    {
        int r = wid * 16 + (sub & 1) * 8 + li;
#pragma unroll
        for (int kc = 0; kc < 4; kc++) {
            int c16 = 2 * kc + (sub >> 1);
            uint32_t a = sb + AT_Q + (uint32_t)(r * 128 + ((c16 ^ (r & 7)) << 4));
            ldsm4(a, qh[kc][0], qh[kc][1], qh[kc][2], qh[kc][3]);
            ldsm4(a + 16384, ql[kc][0], ql[kc][1], ql[kc][2], ql[kc][3]);
        }
    }

    float oacc[8][4];
#pragma unroll
    for (int i = 0; i < 8; i++)
#pragma unroll
        for (int j = 0; j < 4; j++) oacc[i][j] = 0.0f;
    float sum0 = 0.0f, sum1 = 0.0f;

    const int rKV = ((sub >> 1) & 1) * 8 + li;
    const int chKV = sub & 1;

    for (int kt = 0; kt < NKT; kt++) {
        if (kt < NKT - 1) { CPWAIT(1); } else { CPWAIT(0); }
        __syncthreads();
        if (kt + 2 < NKT) { LOAD_KV((kt + 2) % 3, kt + 2); CPCOMMIT(); }

        const uint32_t st = sb + (uint32_t)(kt % 3) * AT_STG;

        // S = Q K^T (scaled Q already applied? no — scale applied via exp arg)
        float sacc[8][4];
#pragma unroll
        for (int i = 0; i < 8; i++)
#pragma unroll
            for (int j = 0; j < 4; j++) sacc[i][j] = 0.0f;

#pragma unroll
        for (int kg = 0; kg < 4; kg++) {
            int row = kg * 16 + rKV;
#pragma unroll
            for (int kc = 0; kc < 4; kc++) {
                int c16 = 2 * kc + chKV;
                uint32_t a = st + (uint32_t)(row * 128 + ((c16 ^ (row & 7)) << 4));
                uint32_t kh[4], kl[4];
                ldsm4(a, kh[0], kh[1], kh[2], kh[3]);
                ldsm4(a + 8192, kl[0], kl[1], kl[2], kl[3]);
#pragma unroll
                for (int hf = 0; hf < 2; hf++) {
                    float* d = sacc[kg * 2 + hf];
                    mma_bf16(d, qh[kc], &kh[hf * 2]);
                    mma_bf16(d, ql[kc], &kh[hf * 2]);
                    mma_bf16(d, qh[kc], &kl[hf * 2]);
                }
            }
        }

        // exp (with 1/8 scale), row sums, pack P, PV
#pragma unroll
        for (int kc = 0; kc < 4; kc++) {
            uint32_t pah[4], pal[4];
#pragma unroll
            for (int half = 0; half < 2; half++) {
                float* cc = sacc[2 * kc + half];
                float p0 = __expf(cc[0] * 0.125f), p1 = __expf(cc[1] * 0.125f);
                float p2 = __expf(cc[2] * 0.125f), p3 = __expf(cc[3] * 0.125f);
                sum0 += p0 + p1; sum1 += p2 + p3;
                __nv_bfloat16 h0, l0, h1, l1, h2, l2, h3, l3;
                bf_split(p0, h0, l0); bf_split(p1, h1, l1);
                bf_split(p2, h2, l2); bf_split(p3, h3, l3);
                pah[half * 2 + 0] = pack_bf(h0, h1);
                pah[half * 2 + 1] = pack_bf(h2, h3);
                pal[half * 2 + 0] = pack_bf(l0, l1);
                pal[half * 2 + 1] = pack_bf(l2, l3);
            }
            // wait: a2,a3 must come from tile 2kc+1; a0,a1 from 2kc — order:
            // half=0 wrote pah[0],pah[1]; half=1 wrote pah[2],pah[3]. Correct.
#pragma unroll
            for (int ng = 0; ng < 4; ng++) {
                int row = ng * 16 + rKV;
                int c16 = 2 * kc + chKV;
                uint32_t a = st + 16384 + (uint32_t)(row * 128 + ((c16 ^ (row & 7)) << 4));
                uint32_t vh[4], vl[4];
                ldsm4(a, vh[0], vh[1], vh[2], vh[3]);
                ldsm4(a + 8192, vl[0], vl[1], vl[2], vl[3]);
#pragma unroll
                for (int hf = 0; hf < 2; hf++) {
                    float* d = oacc[ng * 2 + hf];
                    mma_bf16(d, pah, &vh[hf * 2]);
                    mma_bf16(d, pal, &vh[hf * 2]);
                    mma_bf16(d, pah, &vl[hf * 2]);
                }
            }
        }
    }
#undef LOAD_KV

    sum0 += __shfl_xor_sync(0xffffffffu, sum0, 1);
    sum0 += __shfl_xor_sync(0xffffffffu, sum0, 2);
    sum1 += __shfl_xor_sync(0xffffffffu, sum1, 1);
    sum1 += __shfl_xor_sync(0xffffffffu, sum1, 2);
    const float inv0 = 1.0f / sum0, inv1 = 1.0f / sum1;

    const int g = lane >> 2, tg = lane & 3;
    const size_t base0 = (size_t)(b * SS + q0 + wid * 16 + g) * DD + h * DHH;
#pragma unroll
    for (int nt = 0; nt < 8; nt++) {
        int col = nt * 8 + 2 * tg;
        float v0 = oacc[nt][0] * inv0, v1 = oacc[nt][1] * inv0;
        float v2 = oacc[nt][2] * inv1, v3 = oacc[nt][3] * inv1;
        __nv_bfloat16 h0, l0, h1, l1, h2, l2, h3, l3;
        bf_split(v0, h0, l0); bf_split(v1, h1, l1);
        bf_split(v2, h2, l2); bf_split(v3, h3, l3);
        *reinterpret_cast<uint32_t*>(&AOh[base0 + col]) = pack_bf(h0, h1);
        *reinterpret_cast<uint32_t*>(&AOl[base0 + col]) = pack_bf(l0, l1);
        *reinterpret_cast<uint32_t*>(&AOh[base0 + (size_t)8 * DD + col]) = pack_bf(h2, h3);
        *reinterpret_cast<uint32_t*>(&AOl[base0 + (size_t)8 * DD + col]) = pack_bf(l2, l3);
    }
}

// ===========================================================================
extern "C" void kernel_launch(void* const* d_in, const int* in_sizes, int n_in,
                              void* d_out, int out_size)
{
    const float* x  = (const float*)d_in[0];
    const float* Wq = (const float*)d_in[1];
    const float* bq = (const float*)d_in[2];
    const float* Wk = (const float*)d_in[3];
    const float* bk = (const float*)d_in[4];
    const float* Wv = (const float*)d_in[5];
    const float* bv = (const float*)d_in[6];
    const float* Wo = (const float*)d_in[7];
    const float* bo = (const float*)d_in[8];
    float* out = (float*)d_out;

    __nv_bfloat16 *xh, *xl, *Wth, *Wtl, *Qh, *Ql, *Kh, *Kl, *Vth, *Vtl, *AOh, *AOl;
    cudaGetSymbolAddress((void**)&xh,  g_xh);  cudaGetSymbolAddress((void**)&xl,  g_xl);
    cudaGetSymbolAddress((void**)&Wth, g_Wth); cudaGetSymbolAddress((void**)&Wtl, g_Wtl);
    cudaGetSymbolAddress((void**)&Qh,  g_Qh);  cudaGetSymbolAddress((void**)&Ql,  g_Ql);
    cudaGetSymbolAddress((void**)&Kh,  g_Kh);  cudaGetSymbolAddress((void**)&Kl,  g_Kl);
    cudaGetSymbolAddress((void**)&Vth, g_Vth); cudaGetSymbolAddress((void**)&Vtl, g_Vtl);
    cudaGetSymbolAddress((void**)&AOh, g_AOh); cudaGetSymbolAddress((void**)&AOl, g_AOl);

    cudaFuncSetAttribute(gemm_bf3, cudaFuncAttributeMaxDynamicSharedMemorySize, GEMM_SMEM);
    cudaFuncSetAttribute(attn_tc, cudaFuncAttributeMaxDynamicSharedMemorySize, ATTN_SMEM);

    // conversions
    conv_split<<<(MM * DD / 4 + 255) / 256, 256>>>(x, xh, xl, MM * DD / 4);
    conv_wt<<<dim3(32, 32, 4), 256>>>(Wq, Wk, Wv, Wo, Wth, Wtl);

    // QKV projections (Q,K: split layout; V: transposed split)
    gemm_bf3<<<dim3(24, 32), 256, GEMM_SMEM>>>(
        xh, xl, Wth, Wtl, bq, bk, bv,
        Qh, Ql, Kh, Kl, Vth, Vtl, (float*)nullptr, 3);

    // attention
    attn_tc<<<dim3(SS / 128, BB * HH), 256, ATTN_SMEM>>>(
        Qh, Ql, Kh, Kl, Vth, Vtl, AOh, AOl);

    // output projection (fp32 out)
    gemm_bf3<<<dim3(8, 32), 256, GEMM_SMEM>>>(
        AOh, AOl, Wth + (size_t)3 * DD * DD, Wtl + (size_t)3 * DD * DD,
        bo, bo, bo,
        (__nv_bfloat16*)nullptr, (__nv_bfloat16*)nullptr,
        (__nv_bfloat16*)nullptr, (__nv_bfloat16*)nullptr,
        (__nv_bfloat16*)nullptr, (__nv_bfloat16*)nullptr, out, 1);
}

// round 9
// speedup vs baseline: 12.5668x; 1.1203x over previous
#include <cuda_runtime.h>
#include <cuda_bf16.h>
#include <cstdint>
#include <math.h>

#define BB 2
#define SS 2048
#define DD 1024
#define HH 16
#define DHH 64
#define MM (BB * SS)

// ---------------- scratch (device globals: allocation-free rule) -----------
__device__ __nv_bfloat16 g_xh[(size_t)MM * DD], g_xl[(size_t)MM * DD];
__device__ __nv_bfloat16 g_Wth[(size_t)4 * DD * DD], g_Wtl[(size_t)4 * DD * DD];
__device__ __nv_bfloat16 g_Qh[(size_t)MM * DD], g_Ql[(size_t)MM * DD];
__device__ __nv_bfloat16 g_Kh[(size_t)MM * DD], g_Kl[(size_t)MM * DD];
__device__ __nv_bfloat16 g_Vth[(size_t)MM * DD], g_Vtl[(size_t)MM * DD];  // [B][D][S]
__device__ __nv_bfloat16 g_AOh[(size_t)MM * DD], g_AOl[(size_t)MM * DD];

// ---------------- helpers --------------------------------------------------
__device__ __forceinline__ uint32_t smem_to_u32(const void* p) {
    uint32_t a;
    asm("{ .reg .u64 t; cvta.to.shared.u64 t, %1; cvt.u32.u64 %0, t; }"
        : "=r"(a) : "l"(p));
    return a;
}
__device__ __forceinline__ void ldsm4(uint32_t addr, uint32_t& r0, uint32_t& r1,
                                      uint32_t& r2, uint32_t& r3) {
    asm volatile("ldmatrix.sync.aligned.m8n8.x4.shared.b16 {%0,%1,%2,%3}, [%4];"
                 : "=r"(r0), "=r"(r1), "=r"(r2), "=r"(r3) : "r"(addr));
}
__device__ __forceinline__ void mma_bf16(float* d, const uint32_t* a, const uint32_t* b) {
    asm volatile(
        "mma.sync.aligned.m16n8k16.row.col.f32.bf16.bf16.f32 "
        "{%0,%1,%2,%3}, {%4,%5,%6,%7}, {%8,%9}, {%0,%1,%2,%3};"
        : "+f"(d[0]), "+f"(d[1]), "+f"(d[2]), "+f"(d[3])
        : "r"(a[0]), "r"(a[1]), "r"(a[2]), "r"(a[3]), "r"(b[0]), "r"(b[1]));
}
__device__ __forceinline__ void bf_split(float x, __nv_bfloat16& h, __nv_bfloat16& l) {
    h = __float2bfloat16(x);
    l = __float2bfloat16(x - __bfloat162float(h));
}
__device__ __forceinline__ uint32_t pack_bf(__nv_bfloat16 a, __nv_bfloat16 b) {
    __nv_bfloat162 t(a, b);
    return *reinterpret_cast<uint32_t*>(&t);
}
#define CPA16(dst, src) \
    asm volatile("cp.async.cg.shared.global [%0], [%1], 16;" :: "r"(dst), "l"(src))
#define CPCOMMIT() asm volatile("cp.async.commit_group;" ::: "memory")
#define CPWAIT(n)  asm volatile("cp.async.wait_group %0;" :: "n"(n) : "memory")

// swizzle for [rows][32 bf16] tiles (64B rows, 4x16B chunks)
__device__ __forceinline__ uint32_t swz(int row, int chunk) {
    return (uint32_t)(row * 64 + ((chunk ^ ((row >> 1) & 3)) << 4));
}
// swizzle for [rows][64 bf16] tiles (128B rows, 8x16B chunks)
__device__ __forceinline__ uint32_t sw8(int row, int c8) {
    return (uint32_t)(row * 128 + ((c8 ^ (row & 7)) << 4));
}

// ---------------- conversion kernels ---------------------------------------
__global__ __launch_bounds__(256) void conv_split(
    const float* __restrict__ X, __nv_bfloat16* __restrict__ H,
    __nv_bfloat16* __restrict__ L, int n4)
{
    int i = blockIdx.x * 256 + threadIdx.x;
    if (i >= n4) return;
    float4 v = reinterpret_cast<const float4*>(X)[i];
    __nv_bfloat16 h0, l0, h1, l1, h2, l2, h3, l3;
    bf_split(v.x, h0, l0); bf_split(v.y, h1, l1);
    bf_split(v.z, h2, l2); bf_split(v.w, h3, l3);
    reinterpret_cast<uint2*>(H)[i] = make_uint2(pack_bf(h0, h1), pack_bf(h2, h3));
    reinterpret_cast<uint2*>(L)[i] = make_uint2(pack_bf(l0, l1), pack_bf(l2, l3));
}

__global__ __launch_bounds__(256) void conv_wt(
    const float* __restrict__ W0, const float* __restrict__ W1,
    const float* __restrict__ W2, const float* __restrict__ W3,
    __nv_bfloat16* __restrict__ H, __nv_bfloat16* __restrict__ L)
{
    __shared__ float t[32][33];
    const int mat = blockIdx.z;
    const float* W = (mat == 0) ? W0 : (mat == 1) ? W1 : (mat == 2) ? W2 : W3;
    const int r0 = blockIdx.y * 32, c0 = blockIdx.x * 32;
    const int tx = threadIdx.x & 31, ty = threadIdx.x >> 5;
#pragma unroll
    for (int j = 0; j < 4; j++)
        t[ty + j * 8][tx] = W[(size_t)(r0 + ty + j * 8) * DD + c0 + tx];
    __syncthreads();
#pragma unroll
    for (int j = 0; j < 4; j++) {
        float v = t[tx][ty + j * 8];
        __nv_bfloat16 h, l; bf_split(v, h, l);
        size_t dst = (size_t)mat * DD * DD + (size_t)(c0 + ty + j * 8) * DD + r0 + tx;
        H[dst] = h; L[dst] = l;
    }
}

// ===========================================================================
// bf16x3 GEMM, pre-converted inputs, cp.async 3-stage ring (prefetch-2),
// 2 CTAs/SM. CTA tile 128x128, BK=32, 8 warps (4Mx2N), warp tile 32x64.
// ===========================================================================
#define STG2 32768
#define GEMM_SMEM (3 * STG2)
#define NCHUNK 32

__global__ __launch_bounds__(256, 2) void gemm_bf3(
    const __nv_bfloat16* __restrict__ Ah, const __nv_bfloat16* __restrict__ Al,
    const __nv_bfloat16* __restrict__ Bth, const __nv_bfloat16* __restrict__ Btl,
    const float* __restrict__ bias0, const float* __restrict__ bias1,
    const float* __restrict__ bias2,
    __nv_bfloat16* __restrict__ C0h, __nv_bfloat16* __restrict__ C0l,
    __nv_bfloat16* __restrict__ C1h, __nv_bfloat16* __restrict__ C1l,
    __nv_bfloat16* __restrict__ C2h, __nv_bfloat16* __restrict__ C2l,
    float* __restrict__ Cf, int nmats)
{
    extern __shared__ char smem[];
    const uint32_t sbase = smem_to_u32(smem);
    const int tid = threadIdx.x;
    const int wid = tid >> 5;
    const int lane = tid & 31;

    const int m = (nmats == 3) ? (int)(blockIdx.x >> 3) : 0;
    const __nv_bfloat16* Bh_g = Bth + (size_t)m * DD * DD;
    const __nv_bfloat16* Bl_g = Btl + (size_t)m * DD * DD;
    const float* bias = (m == 0) ? bias0 : (m == 1) ? bias1 : bias2;
    const int bCol = (blockIdx.x & 7) * 128;
    const int bRow = blockIdx.y * 128;

    const int warpM = (wid >> 1) * 32;
    const int warpN = (wid & 1) * 64;
    const int sub = lane >> 3;
    const int li = lane & 7;

    int rA[2]; uint32_t baseA[2]; int swA[2];
#pragma unroll
    for (int fm = 0; fm < 2; fm++) {
        rA[fm] = warpM + fm * 16 + (sub & 1) * 8 + li;
        baseA[fm] = (uint32_t)(rA[fm] * 64);
        swA[fm] = (rA[fm] >> 1) & 3;
    }
    const int chA_off = sub >> 1;
    int rB[4]; uint32_t baseB[4]; int swB[4];
#pragma unroll
    for (int nb = 0; nb < 4; nb++) {
        rB[nb] = warpN + nb * 16 + ((sub >> 1) & 1) * 8 + li;
        baseB[nb] = (uint32_t)(rB[nb] * 64);
        swB[nb] = (rB[nb] >> 1) & 3;
    }
    const int chB_off = sub & 1;

    float acc[2][8][4];
#pragma unroll
    for (int fm = 0; fm < 2; fm++)
#pragma unroll
        for (int fn = 0; fn < 8; fn++)
#pragma unroll
            for (int r = 0; r < 4; r++) acc[fm][fn][r] = 0.0f;

#define LOAD_STAGE(s, c) do { \
        uint32_t st_ = sbase + (uint32_t)(s) * STG2; \
        _Pragma("unroll") \
        for (int p = 0; p < 2; p++) { \
            int id = tid + p * 256; \
            int row = id >> 2, c4 = id & 3; \
            size_t ga = (size_t)(bRow + row) * DD + (c) * 32 + c4 * 8; \
            uint32_t da = st_ + swz(row, c4); \
            CPA16(da, Ah + ga); \
            CPA16(da + 8192, Al + ga); \
            size_t gb = (size_t)(bCol + row) * DD + (c) * 32 + c4 * 8; \
            uint32_t db = st_ + 16384 + swz(row, c4); \
            CPA16(db, Bh_g + gb); \
            CPA16(db + 8192, Bl_g + gb); \
        } \
    } while (0)

    LOAD_STAGE(0, 0); CPCOMMIT();
    LOAD_STAGE(1, 1); CPCOMMIT();

    for (int c = 0; c < NCHUNK; c++) {
        if (c < NCHUNK - 1) { CPWAIT(1); } else { CPWAIT(0); }
        __syncthreads();
        if (c + 2 < NCHUNK) { LOAD_STAGE((c + 2) % 3, c + 2); CPCOMMIT(); }

        const uint32_t st = sbase + (uint32_t)(c % 3) * STG2;
#pragma unroll
        for (int ks = 0; ks < 2; ks++) {
            uint32_t ah[2][4], al[2][4];
#pragma unroll
            for (int fm = 0; fm < 2; fm++) {
                uint32_t chunk = (uint32_t)((2 * ks + chA_off) ^ swA[fm]) << 4;
                ldsm4(st + baseA[fm] + chunk, ah[fm][0], ah[fm][1], ah[fm][2], ah[fm][3]);
                ldsm4(st + 8192 + baseA[fm] + chunk, al[fm][0], al[fm][1], al[fm][2], al[fm][3]);
            }
#pragma unroll
            for (int nb = 0; nb < 4; nb++) {
                // just-in-time B fragments (keeps live registers low)
                uint32_t bh[4], bl[4];
                uint32_t chunk = (uint32_t)((2 * ks + chB_off) ^ swB[nb]) << 4;
                ldsm4(st + 16384 + baseB[nb] + chunk, bh[0], bh[1], bh[2], bh[3]);
                ldsm4(st + 24576 + baseB[nb] + chunk, bl[0], bl[1], bl[2], bl[3]);
#pragma unroll
                for (int fm = 0; fm < 2; fm++)
#pragma unroll
                    for (int hf = 0; hf < 2; hf++) {
                        float* d = acc[fm][nb * 2 + hf];
                        mma_bf16(d, ah[fm], &bh[hf * 2]);
                        mma_bf16(d, al[fm], &bh[hf * 2]);
                        mma_bf16(d, ah[fm], &bl[hf * 2]);
                    }
            }
        }
        __syncthreads();
    }
#undef LOAD_STAGE

    // epilogue
    __nv_bfloat16* Ch = (m == 0) ? C0h : (m == 1) ? C1h : C2h;
    __nv_bfloat16* Cl = (m == 0) ? C0l : (m == 1) ? C1l : C2l;
#pragma unroll
    for (int fm = 0; fm < 2; fm++) {
        int row0 = bRow + warpM + fm * 16 + (lane >> 2);
#pragma unroll
        for (int fn = 0; fn < 8; fn++) {
            int col = bCol + warpN + fn * 8 + 2 * (lane & 3);
            float bx = bias[col], by = bias[col + 1];
            float v[4] = {acc[fm][fn][0] + bx, acc[fm][fn][1] + by,
                          acc[fm][fn][2] + bx, acc[fm][fn][3] + by};
            if (nmats == 1) {
                *reinterpret_cast<float2*>(&Cf[(size_t)row0 * DD + col]) =
                    make_float2(v[0], v[1]);
                *reinterpret_cast<float2*>(&Cf[(size_t)(row0 + 8) * DD + col]) =
                    make_float2(v[2], v[3]);
            } else if (m < 2) {
                __nv_bfloat16 h[4], l[4];
#pragma unroll
                for (int j = 0; j < 4; j++) bf_split(v[j], h[j], l[j]);
                *reinterpret_cast<uint32_t*>(&Ch[(size_t)row0 * DD + col]) = pack_bf(h[0], h[1]);
                *reinterpret_cast<uint32_t*>(&Cl[(size_t)row0 * DD + col]) = pack_bf(l[0], l[1]);
                *reinterpret_cast<uint32_t*>(&Ch[(size_t)(row0 + 8) * DD + col]) = pack_bf(h[2], h[3]);
                *reinterpret_cast<uint32_t*>(&Cl[(size_t)(row0 + 8) * DD + col]) = pack_bf(l[2], l[3]);
            } else {
                // transposed: Vt[b][d][s]
#pragma unroll
                for (int j = 0; j < 4; j++) {
                    int r = row0 + (j >> 1) * 8;
                    int cc = col + (j & 1);
                    size_t idx = ((size_t)(r >> 11) * DD + cc) * SS + (r & (SS - 1));
                    __nv_bfloat16 h, l; bf_split(v[j], h, l);
                    Ch[idx] = h; Cl[idx] = l;
                }
            }
        }
    }
}

// ===========================================================================
// Tensor-core flash attention (bf16x3). CTA = 128 q rows of one (b,h).
// Q staged through stage-2 of the 3-stage K/V ring (fragments extracted to
// registers before the ring reuses it) -> 96KB smem, 2 CTAs/SM.
// ===========================================================================
#define AT_STG 32768          // Kh 0 | Kl 8192 | Vh 16384 | Vl 24576
#define ATTN_SMEM (3 * AT_STG)
#define NKT 32

__global__ __launch_bounds__(256, 2) void attn_tc(
    const __nv_bfloat16* __restrict__ Qh_g, const __nv_bfloat16* __restrict__ Ql_g,
    const __nv_bfloat16* __restrict__ Kh_g, const __nv_bfloat16* __restrict__ Kl_g,
    const __nv_bfloat16* __restrict__ Vth_g, const __nv_bfloat16* __restrict__ Vtl_g,
    __nv_bfloat16* __restrict__ AOh, __nv_bfloat16* __restrict__ AOl)
{
    extern __shared__ char smem[];
    const uint32_t sb = smem_to_u32(smem);
    const int tid = threadIdx.x;
    const int wid = tid >> 5;
    const int lane = tid & 31;
    const int sub = lane >> 3;
    const int li = lane & 7;
    const int bh = blockIdx.y;
    const int b = bh >> 4, h = bh & 15;
    const int q0 = blockIdx.x * 128;

    // Q tile -> stage-2 region (hi at +0, lo at +16384)
    const uint32_t qreg = sb + 2 * AT_STG;
#pragma unroll
    for (int p = 0; p < 4; p++) {
        int id = tid + p * 256;            // 0..1023
        int row = id >> 3, c8 = id & 7;
        size_t src = (size_t)(b * SS + q0 + row) * DD + h * DHH + c8 * 8;
        CPA16(qreg + sw8(row, c8), Qh_g + src);
        CPA16(qreg + 16384 + sw8(row, c8), Ql_g + src);
    }
    CPCOMMIT();

#define LOAD_KV(s, kt) do { \
        uint32_t st_ = sb + (uint32_t)(s) * AT_STG; \
        _Pragma("unroll") \
        for (int p = 0; p < 2; p++) { \
            int id = tid + p * 256; \
            int row = id >> 3, c8 = id & 7; \
            size_t ks_ = (size_t)(b * SS + (kt) * 64 + row) * DD + h * DHH + c8 * 8; \
            CPA16(st_ + sw8(row, c8), Kh_g + ks_); \
            CPA16(st_ + 8192 + sw8(row, c8), Kl_g + ks_); \
            size_t vs_ = (size_t)(b * DD + h * DHH + row) * SS + (kt) * 64 + c8 * 8; \
            CPA16(st_ + 16384 + sw8(row, c8), Vth_g + vs_); \
            CPA16(st_ + 24576 + sw8(row, c8), Vtl_g + vs_); \
        } \
    } while (0)

    LOAD_KV(0, 0); CPCOMMIT();
    LOAD_KV(1, 1); CPCOMMIT();

    CPWAIT(2);          // Q arrived
    __syncthreads();

    // Q fragments for all 4 k-chunks (d=64), hi+lo -> registers
    uint32_t qh[4][4], ql[4][4];
    {
        int r = wid * 16 + (sub & 1) * 8 + li;
#pragma unroll
        for (int kc = 0; kc < 4; kc++) {
            int c16 = 2 * kc + (sub >> 1);
            uint32_t a = qreg + (uint32_t)(r * 128 + ((c16 ^ (r & 7)) << 4));
            ldsm4(a, qh[kc][0], qh[kc][1], qh[kc][2], qh[kc][3]);
            ldsm4(a + 16384, ql[kc][0], ql[kc][1], ql[kc][2], ql[kc][3]);
        }
    }

    float oacc[8][4];
#pragma unroll
    for (int i = 0; i < 8; i++)
#pragma unroll
        for (int j = 0; j < 4; j++) oacc[i][j] = 0.0f;
    float sum0 = 0.0f, sum1 = 0.0f;

    const int rKV = ((sub >> 1) & 1) * 8 + li;
    const int chKV = sub & 1;

    for (int kt = 0; kt < NKT; kt++) {
        if (kt < NKT - 1) { CPWAIT(1); } else { CPWAIT(0); }
        __syncthreads();
        // stage (kt+2)%3 held kt-1 (all warps synced past it); Q fragments
        // were extracted before the loop, so stage 2 is reusable at kt=0.
        if (kt + 2 < NKT) { LOAD_KV((kt + 2) % 3, kt + 2); CPCOMMIT(); }

        const uint32_t st = sb + (uint32_t)(kt % 3) * AT_STG;

        float sacc[8][4];
#pragma unroll
        for (int i = 0; i < 8; i++)
#pragma unroll
            for (int j = 0; j < 4; j++) sacc[i][j] = 0.0f;

#pragma unroll
        for (int kg = 0; kg < 4; kg++) {
            int row = kg * 16 + rKV;
#pragma unroll
            for (int kc = 0; kc < 4; kc++) {
                int c16 = 2 * kc + chKV;
                uint32_t a = st + (uint32_t)(row * 128 + ((c16 ^ (row & 7)) << 4));
                uint32_t kh[4], kl[4];
                ldsm4(a, kh[0], kh[1], kh[2], kh[3]);
                ldsm4(a + 8192, kl[0], kl[1], kl[2], kl[3]);
#pragma unroll
                for (int hf = 0; hf < 2; hf++) {
                    float* d = sacc[kg * 2 + hf];
                    mma_bf16(d, qh[kc], &kh[hf * 2]);
                    mma_bf16(d, ql[kc], &kh[hf * 2]);
                    mma_bf16(d, qh[kc], &kl[hf * 2]);
                }
            }
        }

        // exp (1/8 scale), row sums, register-resident P repack, PV
#pragma unroll
        for (int kc = 0; kc < 4; kc++) {
            uint32_t pah[4], pal[4];
#pragma unroll
            for (int half = 0; half < 2; half++) {
                float* cc = sacc[2 * kc + half];
                float p0 = __expf(cc[0] * 0.125f), p1 = __expf(cc[1] * 0.125f);
                float p2 = __expf(cc[2] * 0.125f), p3 = __expf(cc[3] * 0.125f);
                sum0 += p0 + p1; sum1 += p2 + p3;
                __nv_bfloat16 h0, l0, h1, l1, h2, l2, h3, l3;
                bf_split(p0, h0, l0); bf_split(p1, h1, l1);
                bf_split(p2, h2, l2); bf_split(p3, h3, l3);
                pah[half * 2 + 0] = pack_bf(h0, h1);
                pah[half * 2 + 1] = pack_bf(h2, h3);
                pal[half * 2 + 0] = pack_bf(l0, l1);
                pal[half * 2 + 1] = pack_bf(l2, l3);
            }
#pragma unroll
            for (int ng = 0; ng < 4; ng++) {
                int row = ng * 16 + rKV;
                int c16 = 2 * kc + chKV;
                uint32_t a = st + 16384 + (uint32_t)(row * 128 + ((c16 ^ (row & 7)) << 4));
                uint32_t vh[4], vl[4];
                ldsm4(a, vh[0], vh[1], vh[2], vh[3]);
                ldsm4(a + 8192, vl[0], vl[1], vl[2], vl[3]);
#pragma unroll
                for (int hf = 0; hf < 2; hf++) {
                    float* d = oacc[ng * 2 + hf];
                    mma_bf16(d, pah, &vh[hf * 2]);
                    mma_bf16(d, pal, &vh[hf * 2]);
                    mma_bf16(d, pah, &vl[hf * 2]);
                }
            }
        }
    }
#undef LOAD_KV

    sum0 += __shfl_xor_sync(0xffffffffu, sum0, 1);
    sum0 += __shfl_xor_sync(0xffffffffu, sum0, 2);
    sum1 += __shfl_xor_sync(0xffffffffu, sum1, 1);
    sum1 += __shfl_xor_sync(0xffffffffu, sum1, 2);
    const float inv0 = 1.0f / sum0, inv1 = 1.0f / sum1;

    const int g = lane >> 2, tg = lane & 3;
    const size_t base0 = (size_t)(b * SS + q0 + wid * 16 + g) * DD + h * DHH;
#pragma unroll
    for (int nt = 0; nt < 8; nt++) {
        int col = nt * 8 + 2 * tg;
        float v0 = oacc[nt][0] * inv0, v1 = oacc[nt][1] * inv0;
        float v2 = oacc[nt][2] * inv1, v3 = oacc[nt][3] * inv1;
        __nv_bfloat16 h0, l0, h1, l1, h2, l2, h3, l3;
        bf_split(v0, h0, l0); bf_split(v1, h1, l1);
        bf_split(v2, h2, l2); bf_split(v3, h3, l3);
        *reinterpret_cast<uint32_t*>(&AOh[base0 + col]) = pack_bf(h0, h1);
        *reinterpret_cast<uint32_t*>(&AOl[base0 + col]) = pack_bf(l0, l1);
        *reinterpret_cast<uint32_t*>(&AOh[base0 + (size_t)8 * DD + col]) = pack_bf(h2, h3);
        *reinterpret_cast<uint32_t*>(&AOl[base0 + (size_t)8 * DD + col]) = pack_bf(l2, l3);
    }
}

// ===========================================================================
extern "C" void kernel_launch(void* const* d_in, const int* in_sizes, int n_in,
                              void* d_out, int out_size)
{
    const float* x  = (const float*)d_in[0];
    const float* Wq = (const float*)d_in[1];
    const float* bq = (const float*)d_in[2];
    const float* Wk = (const float*)d_in[3];
    const float* bk = (const float*)d_in[4];
    const float* Wv = (const float*)d_in[5];
    const float* bv = (const float*)d_in[6];
    const float* Wo = (const float*)d_in[7];
    const float* bo = (const float*)d_in[8];
    float* out = (float*)d_out;

    __nv_bfloat16 *xh, *xl, *Wth, *Wtl, *Qh, *Ql, *Kh, *Kl, *Vth, *Vtl, *AOh, *AOl;
    cudaGetSymbolAddress((void**)&xh,  g_xh);  cudaGetSymbolAddress((void**)&xl,  g_xl);
    cudaGetSymbolAddress((void**)&Wth, g_Wth); cudaGetSymbolAddress((void**)&Wtl, g_Wtl);
    cudaGetSymbolAddress((void**)&Qh,  g_Qh);  cudaGetSymbolAddress((void**)&Ql,  g_Ql);
    cudaGetSymbolAddress((void**)&Kh,  g_Kh);  cudaGetSymbolAddress((void**)&Kl,  g_Kl);
    cudaGetSymbolAddress((void**)&Vth, g_Vth); cudaGetSymbolAddress((void**)&Vtl, g_Vtl);
    cudaGetSymbolAddress((void**)&AOh, g_AOh); cudaGetSymbolAddress((void**)&AOl, g_AOl);

    cudaFuncSetAttribute(gemm_bf3, cudaFuncAttributeMaxDynamicSharedMemorySize, GEMM_SMEM);
    cudaFuncSetAttribute(attn_tc, cudaFuncAttributeMaxDynamicSharedMemorySize, ATTN_SMEM);

    // conversions
    conv_split<<<(MM * DD / 4 + 255) / 256, 256>>>(x, xh, xl, MM * DD / 4);
    conv_wt<<<dim3(32, 32, 4), 256>>>(Wq, Wk, Wv, Wo, Wth, Wtl);

    // QKV projections (Q,K: split layout; V: transposed split)
    gemm_bf3<<<dim3(24, 32), 256, GEMM_SMEM>>>(
        xh, xl, Wth, Wtl, bq, bk, bv,
        Qh, Ql, Kh, Kl, Vth, Vtl, (float*)nullptr, 3);

    // attention
    attn_tc<<<dim3(SS / 128, BB * HH), 256, ATTN_SMEM>>>(
        Qh, Ql, Kh, Kl, Vth, Vtl, AOh, AOl);

    // output projection (fp32 out)
    gemm_bf3<<<dim3(8, 32), 256, GEMM_SMEM>>>(
        AOh, AOl, Wth + (size_t)3 * DD * DD, Wtl + (size_t)3 * DD * DD,
        bo, bo, bo,
        (__nv_bfloat16*)nullptr, (__nv_bfloat16*)nullptr,
        (__nv_bfloat16*)nullptr, (__nv_bfloat16*)nullptr,
        (__nv_bfloat16*)nullptr, (__nv_bfloat16*)nullptr, out, 1);
}

// round 12
// speedup vs baseline: 14.8007x; 1.1778x over previous
#include <cuda_runtime.h>
#include <cuda_bf16.h>
#include <cuda_fp16.h>
#include <cstdint>
#include <math.h>

#define BB 2
#define SS 2048
#define DD 1024
#define HH 16
#define DHH 64
#define MM (BB * SS)

// ---------------- scratch (device globals: allocation-free rule) -----------
__device__ __nv_bfloat16 g_xh[(size_t)MM * DD], g_xl[(size_t)MM * DD];
__device__ __nv_bfloat16 g_Wth[(size_t)4 * DD * DD], g_Wtl[(size_t)4 * DD * DD];
__device__ __half g_Qh[(size_t)MM * DD], g_Ql[(size_t)MM * DD];
__device__ __half g_Kh[(size_t)MM * DD];
__device__ __half g_Vth[(size_t)MM * DD], g_Vtl[(size_t)MM * DD];  // [B][D][S]
__device__ __nv_bfloat16 g_AOh[(size_t)MM * DD], g_AOl[(size_t)MM * DD];

// ---------------- helpers --------------------------------------------------
__device__ __forceinline__ uint32_t smem_to_u32(const void* p) {
    uint32_t a;
    asm("{ .reg .u64 t; cvta.to.shared.u64 t, %1; cvt.u32.u64 %0, t; }"
        : "=r"(a) : "l"(p));
    return a;
}
__device__ __forceinline__ void ldsm4(uint32_t addr, uint32_t& r0, uint32_t& r1,
                                      uint32_t& r2, uint32_t& r3) {
    asm volatile("ldmatrix.sync.aligned.m8n8.x4.shared.b16 {%0,%1,%2,%3}, [%4];"
                 : "=r"(r0), "=r"(r1), "=r"(r2), "=r"(r3) : "r"(addr));
}
__device__ __forceinline__ void mma_bf16(float* d, const uint32_t* a, const uint32_t* b) {
    asm volatile(
        "mma.sync.aligned.m16n8k16.row.col.f32.bf16.bf16.f32 "
        "{%0,%1,%2,%3}, {%4,%5,%6,%7}, {%8,%9}, {%0,%1,%2,%3};"
        : "+f"(d[0]), "+f"(d[1]), "+f"(d[2]), "+f"(d[3])
        : "r"(a[0]), "r"(a[1]), "r"(a[2]), "r"(a[3]), "r"(b[0]), "r"(b[1]));
}
__device__ __forceinline__ void mma_f16(float* d, const uint32_t* a, const uint32_t* b) {
    asm volatile(
        "mma.sync.aligned.m16n8k16.row.col.f32.f16.f16.f32 "
        "{%0,%1,%2,%3}, {%4,%5,%6,%7}, {%8,%9}, {%0,%1,%2,%3};"
        : "+f"(d[0]), "+f"(d[1]), "+f"(d[2]), "+f"(d[3])
        : "r"(a[0]), "r"(a[1]), "r"(a[2]), "r"(a[3]), "r"(b[0]), "r"(b[1]));
}
__device__ __forceinline__ void bf_split(float x, __nv_bfloat16& h, __nv_bfloat16& l) {
    h = __float2bfloat16(x);
    l = __float2bfloat16(x - __bfloat162float(h));
}
__device__ __forceinline__ void hf_split(float x, __half& h, __half& l) {
    h = __float2half_rn(x);
    l = __float2half_rn(x - __half2float(h));
}
__device__ __forceinline__ uint32_t pack_bf(__nv_bfloat16 a, __nv_bfloat16 b) {
    __nv_bfloat162 t(a, b);
    return *reinterpret_cast<uint32_t*>(&t);
}
__device__ __forceinline__ uint32_t pack_h2(__half a, __half b) {
    __half2 t(a, b);
    return *reinterpret_cast<uint32_t*>(&t);
}
__device__ __forceinline__ uint32_t pack_f2h2(float a, float b) {
    __half2 t = __floats2half2_rn(a, b);
    return *reinterpret_cast<uint32_t*>(&t);
}
#define CPA16(dst, src) \
    asm volatile("cp.async.cg.shared.global [%0], [%1], 16;" :: "r"(dst), "l"(src))
#define CPCOMMIT() asm volatile("cp.async.commit_group;" ::: "memory")
#define CPWAIT(n)  asm volatile("cp.async.wait_group %0;" :: "n"(n) : "memory")

// swizzle for [rows][32 x 16-bit] tiles (64B rows, 4x16B chunks)
__device__ __forceinline__ uint32_t swz(int row, int chunk) {
    return (uint32_t)(row * 64 + ((chunk ^ ((row >> 1) & 3)) << 4));
}
// swizzle for [rows][64 x 16-bit] tiles (128B rows, 8x16B chunks)
__device__ __forceinline__ uint32_t sw8(int row, int c8) {
    return (uint32_t)(row * 128 + ((c8 ^ (row & 7)) << 4));
}

// ---------------- conversion kernels ---------------------------------------
__global__ __launch_bounds__(256) void conv_split(
    const float* __restrict__ X, __nv_bfloat16* __restrict__ H,
    __nv_bfloat16* __restrict__ L, int n4)
{
    int i = blockIdx.x * 256 + threadIdx.x;
    if (i >= n4) return;
    float4 v = reinterpret_cast<const float4*>(X)[i];
    __nv_bfloat16 h0, l0, h1, l1, h2, l2, h3, l3;
    bf_split(v.x, h0, l0); bf_split(v.y, h1, l1);
    bf_split(v.z, h2, l2); bf_split(v.w, h3, l3);
    reinterpret_cast<uint2*>(H)[i] = make_uint2(pack_bf(h0, h1), pack_bf(h2, h3));
    reinterpret_cast<uint2*>(L)[i] = make_uint2(pack_bf(l0, l1), pack_bf(l2, l3));
}

__global__ __launch_bounds__(256) void conv_wt(
    const float* __restrict__ W0, const float* __restrict__ W1,
    const float* __restrict__ W2, const float* __restrict__ W3,
    __nv_bfloat16* __restrict__ H, __nv_bfloat16* __restrict__ L)
{
    __shared__ float t[32][33];
    const int mat = blockIdx.z;
    const float* W = (mat == 0) ? W0 : (mat == 1) ? W1 : (mat == 2) ? W2 : W3;
    const int r0 = blockIdx.y * 32, c0 = blockIdx.x * 32;
    const int tx = threadIdx.x & 31, ty = threadIdx.x >> 5;
#pragma unroll
    for (int j = 0; j < 4; j++)
        t[ty + j * 8][tx] = W[(size_t)(r0 + ty + j * 8) * DD + c0 + tx];
    __syncthreads();
#pragma unroll
    for (int j = 0; j < 4; j++) {
        float v = t[tx][ty + j * 8];
        __nv_bfloat16 h, l; bf_split(v, h, l);
        size_t dst = (size_t)mat * DD * DD + (size_t)(c0 + ty + j * 8) * DD + r0 + tx;
        H[dst] = h; L[dst] = l;
    }
}

// ===========================================================================
// bf16x3 GEMM, pre-converted inputs, cp.async 3-stage ring, single barrier
// per chunk, 2 CTAs/SM. CTA tile 128x128, BK=32, 8 warps (4Mx2N).
// Outputs: m=0 -> Q (fp16 hi/lo), m=1 -> K (fp16 hi only),
//          m=2 -> V transposed (fp16 hi/lo), nmats==1 -> fp32 Cf.
// ===========================================================================
#define STG2 32768
#define GEMM_SMEM (3 * STG2)
#define NCHUNK 32

__global__ __launch_bounds__(256, 2) void gemm_bf3(
    const __nv_bfloat16* __restrict__ Ah, const __nv_bfloat16* __restrict__ Al,
    const __nv_bfloat16* __restrict__ Bth, const __nv_bfloat16* __restrict__ Btl,
    const float* __restrict__ bias0, const float* __restrict__ bias1,
    const float* __restrict__ bias2,
    __half* __restrict__ Qh, __half* __restrict__ Ql,
    __half* __restrict__ Kh,
    __half* __restrict__ Vth, __half* __restrict__ Vtl,
    float* __restrict__ Cf, int nmats)
{
    extern __shared__ char smem[];
    const uint32_t sbase = smem_to_u32(smem);
    const int tid = threadIdx.x;
    const int wid = tid >> 5;
    const int lane = tid & 31;

    const int m = (nmats == 3) ? (int)(blockIdx.x >> 3) : 0;
    const __nv_bfloat16* Bh_g = Bth + (size_t)m * DD * DD;
    const __nv_bfloat16* Bl_g = Btl + (size_t)m * DD * DD;
    const float* bias = (m == 0) ? bias0 : (m == 1) ? bias1 : bias2;
    const int bCol = (blockIdx.x & 7) * 128;
    const int bRow = blockIdx.y * 128;

    const int warpM = (wid >> 1) * 32;
    const int warpN = (wid & 1) * 64;
    const int sub = lane >> 3;
    const int li = lane & 7;

    int rA[2]; uint32_t baseA[2]; int swA[2];
#pragma unroll
    for (int fm = 0; fm < 2; fm++) {
        rA[fm] = warpM + fm * 16 + (sub & 1) * 8 + li;
        baseA[fm] = (uint32_t)(rA[fm] * 64);
        swA[fm] = (rA[fm] >> 1) & 3;
    }
    const int chA_off = sub >> 1;
    int rB[4]; uint32_t baseB[4]; int swB[4];
#pragma unroll
    for (int nb = 0; nb < 4; nb++) {
        rB[nb] = warpN + nb * 16 + ((sub >> 1) & 1) * 8 + li;
        baseB[nb] = (uint32_t)(rB[nb] * 64);
        swB[nb] = (rB[nb] >> 1) & 3;
    }
    const int chB_off = sub & 1;

    float acc[2][8][4];
#pragma unroll
    for (int fm = 0; fm < 2; fm++)
#pragma unroll
        for (int fn = 0; fn < 8; fn++)
#pragma unroll
            for (int r = 0; r < 4; r++) acc[fm][fn][r] = 0.0f;

#define LOAD_STAGE(s, c) do { \
        uint32_t st_ = sbase + (uint32_t)(s) * STG2; \
        _Pragma("unroll") \
        for (int p = 0; p < 2; p++) { \
            int id = tid + p * 256; \
            int row = id >> 2, c4 = id & 3; \
            size_t ga = (size_t)(bRow + row) * DD + (c) * 32 + c4 * 8; \
            uint32_t da = st_ + swz(row, c4); \
            CPA16(da, Ah + ga); \
            CPA16(da + 8192, Al + ga); \
            size_t gb = (size_t)(bCol + row) * DD + (c) * 32 + c4 * 8; \
            uint32_t db = st_ + 16384 + swz(row, c4); \
            CPA16(db, Bh_g + gb); \
            CPA16(db + 8192, Bl_g + gb); \
        } \
    } while (0)

    LOAD_STAGE(0, 0); CPCOMMIT();
    LOAD_STAGE(1, 1); CPCOMMIT();

    for (int c = 0; c < NCHUNK; c++) {
        if (c < NCHUNK - 1) { CPWAIT(1); } else { CPWAIT(0); }
        __syncthreads();
        // After this barrier every warp finished chunk c-1's reads of stage
        // (c-1)%3 == (c+2)%3, so refilling it is safe; single sync per chunk.
        if (c + 2 < NCHUNK) { LOAD_STAGE((c + 2) % 3, c + 2); CPCOMMIT(); }

        const uint32_t st = sbase + (uint32_t)(c % 3) * STG2;
#pragma unroll
        for (int ks = 0; ks < 2; ks++) {
            uint32_t ah[2][4], al[2][4];
#pragma unroll
            for (int fm = 0; fm < 2; fm++) {
                uint32_t chunk = (uint32_t)((2 * ks + chA_off) ^ swA[fm]) << 4;
                ldsm4(st + baseA[fm] + chunk, ah[fm][0], ah[fm][1], ah[fm][2], ah[fm][3]);
                ldsm4(st + 8192 + baseA[fm] + chunk, al[fm][0], al[fm][1], al[fm][2], al[fm][3]);
            }
#pragma unroll
            for (int nb = 0; nb < 4; nb++) {
                uint32_t bh[4], bl[4];
                uint32_t chunk = (uint32_t)((2 * ks + chB_off) ^ swB[nb]) << 4;
                ldsm4(st + 16384 + baseB[nb] + chunk, bh[0], bh[1], bh[2], bh[3]);
                ldsm4(st + 24576 + baseB[nb] + chunk, bl[0], bl[1], bl[2], bl[3]);
#pragma unroll
                for (int fm = 0; fm < 2; fm++)
#pragma unroll
                    for (int hf = 0; hf < 2; hf++) {
                        float* d = acc[fm][nb * 2 + hf];
                        mma_bf16(d, ah[fm], &bh[hf * 2]);
                        mma_bf16(d, al[fm], &bh[hf * 2]);
                        mma_bf16(d, ah[fm], &bl[hf * 2]);
                    }
            }
        }
    }
#undef LOAD_STAGE

    // epilogue
#pragma unroll
    for (int fm = 0; fm < 2; fm++) {
        int row0 = bRow + warpM + fm * 16 + (lane >> 2);
#pragma unroll
        for (int fn = 0; fn < 8; fn++) {
            int col = bCol + warpN + fn * 8 + 2 * (lane & 3);
            float bx = bias[col], by = bias[col + 1];
            float v[4] = {acc[fm][fn][0] + bx, acc[fm][fn][1] + by,
                          acc[fm][fn][2] + bx, acc[fm][fn][3] + by};
            if (nmats == 1) {
                *reinterpret_cast<float2*>(&Cf[(size_t)row0 * DD + col]) =
                    make_float2(v[0], v[1]);
                *reinterpret_cast<float2*>(&Cf[(size_t)(row0 + 8) * DD + col]) =
                    make_float2(v[2], v[3]);
            } else if (m == 0) {
                __half h[4], l[4];
#pragma unroll
                for (int j = 0; j < 4; j++) hf_split(v[j], h[j], l[j]);
                *reinterpret_cast<uint32_t*>(&Qh[(size_t)row0 * DD + col]) = pack_h2(h[0], h[1]);
                *reinterpret_cast<uint32_t*>(&Ql[(size_t)row0 * DD + col]) = pack_h2(l[0], l[1]);
                *reinterpret_cast<uint32_t*>(&Qh[(size_t)(row0 + 8) * DD + col]) = pack_h2(h[2], h[3]);
                *reinterpret_cast<uint32_t*>(&Ql[(size_t)(row0 + 8) * DD + col]) = pack_h2(l[2], l[3]);
            } else if (m == 1) {
                *reinterpret_cast<uint32_t*>(&Kh[(size_t)row0 * DD + col]) = pack_f2h2(v[0], v[1]);
                *reinterpret_cast<uint32_t*>(&Kh[(size_t)(row0 + 8) * DD + col]) = pack_f2h2(v[2], v[3]);
            } else {
                // transposed: Vt[b][d][s], fp16 hi/lo
#pragma unroll
                for (int j = 0; j < 4; j++) {
                    int r = row0 + (j >> 1) * 8;
                    int cc = col + (j & 1);
                    size_t idx = ((size_t)(r >> 11) * DD + cc) * SS + (r & (SS - 1));
                    __half h, l; hf_split(v[j], h, l);
                    Vth[idx] = h; Vtl[idx] = l;
                }
            }
        }
    }
}

// ===========================================================================
// Tensor-core flash attention, fp16 2-term. CTA = 128 q rows of one (b,h).
// S = (q_h + q_l) . k_h  (2 MMAs);  O += p_h . (v_h + v_l)  (2 MMAs).
// Stage: Kh 8KB | Vh 8KB | Vl 8KB = 24KB; 3 stages + 32KB Q = 104KB smem.
// ===========================================================================
#define AT_STG 24576
#define AT_Q   (3 * AT_STG)
#define ATTN_SMEM (3 * AT_STG + 32768)
#define NKT 32

__global__ __launch_bounds__(256, 2) void attn_tc(
    const __half* __restrict__ Qh_g, const __half* __restrict__ Ql_g,
    const __half* __restrict__ Kh_g,
    const __half* __restrict__ Vth_g, const __half* __restrict__ Vtl_g,
    __nv_bfloat16* __restrict__ AOh, __nv_bfloat16* __restrict__ AOl)
{
    extern __shared__ char smem[];
    const uint32_t sb = smem_to_u32(smem);
    const int tid = threadIdx.x;
    const int wid = tid >> 5;
    const int lane = tid & 31;
    const int sub = lane >> 3;
    const int li = lane & 7;
    const int bh = blockIdx.y;
    const int b = bh >> 4, h = bh & 15;
    const int q0 = blockIdx.x * 128;

    // Q tile (hi at +0, lo at +16384)
    const uint32_t qreg = sb + AT_Q;
#pragma unroll
    for (int p = 0; p < 4; p++) {
        int id = tid + p * 256;            // 0..1023
        int row = id >> 3, c8 = id & 7;
        size_t src = (size_t)(b * SS + q0 + row) * DD + h * DHH + c8 * 8;
        CPA16(qreg + sw8(row, c8), Qh_g + src);
        CPA16(qreg + 16384 + sw8(row, c8), Ql_g + src);
    }
    CPCOMMIT();

#define LOAD_KV(s, kt) do { \
        uint32_t st_ = sb + (uint32_t)(s) * AT_STG; \
        _Pragma("unroll") \
        for (int p = 0; p < 2; p++) { \
            int id = tid + p * 256; \
            int row = id >> 3, c8 = id & 7; \
            size_t ks_ = (size_t)(b * SS + (kt) * 64 + row) * DD + h * DHH + c8 * 8; \
            CPA16(st_ + sw8(row, c8), Kh_g + ks_); \
            size_t vs_ = (size_t)(b * DD + h * DHH + row) * SS + (kt) * 64 + c8 * 8; \
            CPA16(st_ + 8192 + sw8(row, c8), Vth_g + vs_); \
            CPA16(st_ + 16384 + sw8(row, c8), Vtl_g + vs_); \
        } \
    } while (0)

    LOAD_KV(0, 0); CPCOMMIT();
    LOAD_KV(1, 1); CPCOMMIT();

    CPWAIT(2);          // Q arrived
    __syncthreads();

    // Q fragments for all 4 k-chunks (d=64), hi+lo -> registers
    uint32_t qh[4][4], ql[4][4];
    {
        int r = wid * 16 + (sub & 1) * 8 + li;
#pragma unroll
        for (int kc = 0; kc < 4; kc++) {
            int c16 = 2 * kc + (sub >> 1);
            uint32_t a = qreg + (uint32_t)(r * 128 + ((c16 ^ (r & 7)) << 4));
            ldsm4(a, qh[kc][0], qh[kc][1], qh[kc][2], qh[kc][3]);
            ldsm4(a + 16384, ql[kc][0], ql[kc][1], ql[kc][2], ql[kc][3]);
        }
    }

    float oacc[8][4];
#pragma unroll
    for (int i = 0; i < 8; i++)
#pragma unroll
        for (int j = 0; j < 4; j++) oacc[i][j] = 0.0f;
    float sum0 = 0.0f, sum1 = 0.0f;

    const int rKV = ((sub >> 1) & 1) * 8 + li;
    const int chKV = sub & 1;

    for (int kt = 0; kt < NKT; kt++) {
        if (kt < NKT - 1) { CPWAIT(1); } else { CPWAIT(0); }
        __syncthreads();
        if (kt + 2 < NKT) { LOAD_KV((kt + 2) % 3, kt + 2); CPCOMMIT(); }

        const uint32_t st = sb + (uint32_t)(kt % 3) * AT_STG;

        float sacc[8][4];
#pragma unroll
        for (int i = 0; i < 8; i++)
#pragma unroll
            for (int j = 0; j < 4; j++) sacc[i][j] = 0.0f;

#pragma unroll
        for (int kg = 0; kg < 4; kg++) {
            int row = kg * 16 + rKV;
#pragma unroll
            for (int kc = 0; kc < 4; kc++) {
                int c16 = 2 * kc + chKV;
                uint32_t a = st + (uint32_t)(row * 128 + ((c16 ^ (row & 7)) << 4));
                uint32_t kh[4];
                ldsm4(a, kh[0], kh[1], kh[2], kh[3]);
#pragma unroll
                for (int hf = 0; hf < 2; hf++) {
                    float* d = sacc[kg * 2 + hf];
                    mma_f16(d, qh[kc], &kh[hf * 2]);
                    mma_f16(d, ql[kc], &kh[hf * 2]);
                }
            }
        }

        // exp (1/8 scale), row sums, fp16 P pack (hi only), PV
#pragma unroll
        for (int kc = 0; kc < 4; kc++) {
            uint32_t pah[4];
#pragma unroll
            for (int half = 0; half < 2; half++) {
                float* cc = sacc[2 * kc + half];
                float p0 = __expf(cc[0] * 0.125f), p1 = __expf(cc[1] * 0.125f);
                float p2 = __expf(cc[2] * 0.125f), p3 = __expf(cc[3] * 0.125f);
                sum0 += p0 + p1; sum1 += p2 + p3;
                pah[half * 2 + 0] = pack_f2h2(p0, p1);
                pah[half * 2 + 1] = pack_f2h2(p2, p3);
            }
#pragma unroll
            for (int ng = 0; ng < 4; ng++) {
                int row = ng * 16 + rKV;
                int c16 = 2 * kc + chKV;
                uint32_t a = st + 8192 + (uint32_t)(row * 128 + ((c16 ^ (row & 7)) << 4));
                uint32_t vh[4], vl[4];
                ldsm4(a, vh[0], vh[1], vh[2], vh[3]);
                ldsm4(a + 8192, vl[0], vl[1], vl[2], vl[3]);
#pragma unroll
                for (int hf = 0; hf < 2; hf++) {
                    float* d = oacc[ng * 2 + hf];
                    mma_f16(d, pah, &vh[hf * 2]);
                    mma_f16(d, pah, &vl[hf * 2]);
                }
            }
        }
    }
#undef LOAD_KV

    sum0 += __shfl_xor_sync(0xffffffffu, sum0, 1);
    sum0 += __shfl_xor_sync(0xffffffffu, sum0, 2);
    sum1 += __shfl_xor_sync(0xffffffffu, sum1, 1);
    sum1 += __shfl_xor_sync(0xffffffffu, sum1, 2);
    const float inv0 = 1.0f / sum0, inv1 = 1.0f / sum1;

    const int g = lane >> 2, tg = lane & 3;
    const size_t base0 = (size_t)(b * SS + q0 + wid * 16 + g) * DD + h * DHH;
#pragma unroll
    for (int nt = 0; nt < 8; nt++) {
        int col = nt * 8 + 2 * tg;
        float v0 = oacc[nt][0] * inv0, v1 = oacc[nt][1] * inv0;
        float v2 = oacc[nt][2] * inv1, v3 = oacc[nt][3] * inv1;
        __nv_bfloat16 h0, l0, h1, l1, h2, l2, h3, l3;
        bf_split(v0, h0, l0); bf_split(v1, h1, l1);
        bf_split(v2, h2, l2); bf_split(v3, h3, l3);
        *reinterpret_cast<uint32_t*>(&AOh[base0 + col]) = pack_bf(h0, h1);
        *reinterpret_cast<uint32_t*>(&AOl[base0 + col]) = pack_bf(l0, l1);
        *reinterpret_cast<uint32_t*>(&AOh[base0 + (size_t)8 * DD + col]) = pack_bf(h2, h3);
        *reinterpret_cast<uint32_t*>(&AOl[base0 + (size_t)8 * DD + col]) = pack_bf(l2, l3);
    }
}

// ===========================================================================
extern "C" void kernel_launch(void* const* d_in, const int* in_sizes, int n_in,
                              void* d_out, int out_size)
{
    const float* x  = (const float*)d_in[0];
    const float* Wq = (const float*)d_in[1];
    const float* bq = (const float*)d_in[2];
    const float* Wk = (const float*)d_in[3];
    const float* bk = (const float*)d_in[4];
    const float* Wv = (const float*)d_in[5];
    const float* bv = (const float*)d_in[6];
    const float* Wo = (const float*)d_in[7];
    const float* bo = (const float*)d_in[8];
    float* out = (float*)d_out;

    __nv_bfloat16 *xh, *xl, *Wth, *Wtl, *AOh, *AOl;
    __half *Qh, *Ql, *Kh, *Vth, *Vtl;
    cudaGetSymbolAddress((void**)&xh,  g_xh);  cudaGetSymbolAddress((void**)&xl,  g_xl);
    cudaGetSymbolAddress((void**)&Wth, g_Wth); cudaGetSymbolAddress((void**)&Wtl, g_Wtl);
    cudaGetSymbolAddress((void**)&Qh,  g_Qh);  cudaGetSymbolAddress((void**)&Ql,  g_Ql);
    cudaGetSymbolAddress((void**)&Kh,  g_Kh);
    cudaGetSymbolAddress((void**)&Vth, g_Vth); cudaGetSymbolAddress((void**)&Vtl, g_Vtl);
    cudaGetSymbolAddress((void**)&AOh, g_AOh); cudaGetSymbolAddress((void**)&AOl, g_AOl);

    cudaFuncSetAttribute(gemm_bf3, cudaFuncAttributeMaxDynamicSharedMemorySize, GEMM_SMEM);
    cudaFuncSetAttribute(attn_tc, cudaFuncAttributeMaxDynamicSharedMemorySize, ATTN_SMEM);

    // conversions
    conv_split<<<(MM * DD / 4 + 255) / 256, 256>>>(x, xh, xl, MM * DD / 4);
    conv_wt<<<dim3(32, 32, 4), 256>>>(Wq, Wk, Wv, Wo, Wth, Wtl);

    // QKV projections (Q: fp16 hi/lo; K: fp16 hi; V: transposed fp16 hi/lo)
    gemm_bf3<<<dim3(24, 32), 256, GEMM_SMEM>>>(
        xh, xl, Wth, Wtl, bq, bk, bv,
        Qh, Ql, Kh, Vth, Vtl, (float*)nullptr, 3);

    // attention (fp16 2-term)
    attn_tc<<<dim3(SS / 128, BB * HH), 256, ATTN_SMEM>>>(
        Qh, Ql, Kh, Vth, Vtl, AOh, AOl);

    // output projection (fp32 out). A = AO (bf16 hi/lo), B = Wo slice.
    gemm_bf3<<<dim3(8, 32), 256, GEMM_SMEM>>>(
        AOh, AOl, Wth + (size_t)3 * DD * DD, Wtl + (size_t)3 * DD * DD,
        bo, bo, bo,
        (__half*)nullptr, (__half*)nullptr, (__half*)nullptr,
        (__half*)nullptr, (__half*)nullptr, out, 1);
}